// round 6
// baseline (speedup 1.0000x reference)
#include <cuda_runtime.h>
#include <cuda_bf16.h>
#include <cstdint>

// Problem constants
#define NN      100000
#define EE      1600000
#define IN_DIM  64
#define HID     128
#define NCLS    18
#define BATCH   8
#define KSEL    5000
#define NPER    (NN / BATCH)   // 12500
#define SORT_M  16384          // next pow2 >= NPER
#define RPB     8              // ranks per block in k_final
#define FIN_BLK (KSEL / RPB)   // 625 blocks per batch

// ---------------- scratch (static device globals; no allocation) ----------------
__device__ float g_bufA[(size_t)NN * HID];   // 51.2 MB
__device__ float g_bufB[(size_t)NN * HID];   // 51.2 MB
__device__ int   g_out_deg[NN];
__device__ int   g_in_deg[NN];
__device__ float g_norm_src[NN];
__device__ float g_norm_dst[NN];
__device__ int   g_row_ptr[NN + 1];
__device__ int   g_pos[NN];
__device__ int   g_csr_src[EE];
__device__ int   g_sel[BATCH * KSEL];                    // sel[b*K + rank] = global node id
__device__ float g_partial[BATCH * FIN_BLK * NCLS];      // deterministic reduction staging

// ---------------- degree / norm ----------------
__global__ void k_zero_deg() {
    int i = blockIdx.x * blockDim.x + threadIdx.x;
    if (i < NN) { g_out_deg[i] = 0; g_in_deg[i] = 0; }
}

__global__ void k_degrees(const int* __restrict__ src, const int* __restrict__ dst) {
    int e = blockIdx.x * blockDim.x + threadIdx.x;
    if (e < EE) {
        atomicAdd(&g_out_deg[src[e]], 1);
        atomicAdd(&g_in_deg[dst[e]], 1);
    }
}

__global__ void k_norms() {
    int i = blockIdx.x * blockDim.x + threadIdx.x;
    if (i < NN) {
        int od = g_out_deg[i]; if (od < 1) od = 1;
        int id = g_in_deg[i];  if (id < 1) id = 1;
        g_norm_src[i] = rsqrtf((float)od);
        g_norm_dst[i] = rsqrtf((float)id);
    }
}

// ---------------- CSR build (counting sort by dst) ----------------
__global__ void k_scan() {
    __shared__ int part[1024];
    int t = threadIdx.x;
    const int per = (NN + 1023) / 1024;  // 98
    int beg = t * per;
    int end = beg + per; if (end > NN) end = NN;
    if (beg > NN) beg = NN;
    int s = 0;
    for (int i = beg; i < end; i++) s += g_in_deg[i];
    part[t] = s;
    __syncthreads();
    for (int off = 1; off < 1024; off <<= 1) {
        int v = (t >= off) ? part[t - off] : 0;
        __syncthreads();
        part[t] += v;
        __syncthreads();
    }
    int run = (t == 0) ? 0 : part[t - 1];
    for (int i = beg; i < end; i++) {
        g_row_ptr[i] = run;
        g_pos[i]     = run;
        run += g_in_deg[i];
    }
    if (t == 1023) g_row_ptr[NN] = run;  // == EE
}

__global__ void k_csr_scatter(const int* __restrict__ src, const int* __restrict__ dst) {
    int e = blockIdx.x * blockDim.x + threadIdx.x;
    if (e < EE) {
        int p = atomicAdd(&g_pos[dst[e]], 1);
        g_csr_src[p] = src[e];
    }
}

// ---------------- 64-dim CSR gather aggregation with fused src-norm ----------
// Hout[v,:] = sum_{e: dst==v} X[csr_src[e],:] * norm_src[csr_src[e]]
__global__ __launch_bounds__(256) void k_agg64(const float* __restrict__ X,
                                               float* __restrict__ Hout) {
    int warp = (blockIdx.x * blockDim.x + threadIdx.x) >> 5;
    int lane = threadIdx.x & 31;
    if (warp >= NN) return;
    int beg = g_row_ptr[warp];
    int end = g_row_ptr[warp + 1];
    float2 acc0 = make_float2(0.f, 0.f);
    float2 acc1 = make_float2(0.f, 0.f);
    int e = beg;
    for (; e + 1 < end; e += 2) {
        int s0 = g_csr_src[e];
        int s1 = g_csr_src[e + 1];
        float n0 = __ldg(&g_norm_src[s0]);
        float n1 = __ldg(&g_norm_src[s1]);
        float2 v0 = __ldg((const float2*)(X + (size_t)s0 * IN_DIM) + lane);
        float2 v1 = __ldg((const float2*)(X + (size_t)s1 * IN_DIM) + lane);
        acc0.x += v0.x * n0; acc0.y += v0.y * n0;
        acc1.x += v1.x * n1; acc1.y += v1.y * n1;
    }
    if (e < end) {
        int s0 = g_csr_src[e];
        float n0 = __ldg(&g_norm_src[s0]);
        float2 v0 = __ldg((const float2*)(X + (size_t)s0 * IN_DIM) + lane);
        acc0.x += v0.x * n0; acc0.y += v0.y * n0;
    }
    acc0.x += acc1.x; acc0.y += acc1.y;
    ((float2*)(Hout + (size_t)warp * IN_DIM))[lane] = acc0;
}

// ---------------- dense transform ----------------
// POST=1: Out[i,:] = relu((A[i,:KD] @ W) * norm_dst[i] + bias)   (layer-1 tail)
// POST=0: Out[i,:] = (A[i,:KD] @ W) * norm_src[i]                (layer-2 head)
template <int KD, int POST>
__global__ __launch_bounds__(256) void k_gemm(const float* __restrict__ A,
                                              const float* __restrict__ W,
                                              const float* __restrict__ bias,
                                              float* __restrict__ Out) {
    const int TM = 64;
    __shared__ float As[TM][32];      // 8 KB
    __shared__ float Bs[32][HID];     // 16 KB
    int t  = threadIdx.x;
    int tx = t & 31;                  // col group: cols tx*4 .. tx*4+3
    int ty = t >> 5;                  // row group: rows ty*8 .. ty*8+7
    int row0 = blockIdx.x * TM;

    float acc[8][4];
#pragma unroll
    for (int r = 0; r < 8; r++)
#pragma unroll
        for (int c = 0; c < 4; c++) acc[r][c] = 0.f;

    for (int kk = 0; kk < KD; kk += 32) {
#pragma unroll
        for (int j = 0; j < 8; j++) {      // 2048 elems of As
            int m = t + j * 256;
            int r = m >> 5, c = m & 31;
            int gr = row0 + r;
            As[r][c] = (gr < NN) ? A[(size_t)gr * KD + kk + c] : 0.f;
        }
#pragma unroll
        for (int j = 0; j < 16; j++) {     // 4096 elems of Bs
            int m = t + j * 256;
            int r = m >> 7, c = m & 127;
            Bs[r][c] = W[(size_t)(kk + r) * HID + c];
        }
        __syncthreads();
#pragma unroll
        for (int k = 0; k < 32; k++) {
            float4 bv = *(const float4*)&Bs[k][tx * 4];
#pragma unroll
            for (int r = 0; r < 8; r++) {
                float a = As[ty * 8 + r][k];
                acc[r][0] += a * bv.x;
                acc[r][1] += a * bv.y;
                acc[r][2] += a * bv.z;
                acc[r][3] += a * bv.w;
            }
        }
        __syncthreads();
    }
#pragma unroll
    for (int r = 0; r < 8; r++) {
        int gr = row0 + ty * 8 + r;
        if (gr < NN) {
            float4 o;
            if (POST) {
                float nd = g_norm_dst[gr];
                float4 b = __ldg((const float4*)bias + tx);
                o.x = fmaxf(acc[r][0] * nd + b.x, 0.f);
                o.y = fmaxf(acc[r][1] * nd + b.y, 0.f);
                o.z = fmaxf(acc[r][2] * nd + b.z, 0.f);
                o.w = fmaxf(acc[r][3] * nd + b.w, 0.f);
            } else {
                float ns = g_norm_src[gr];
                o.x = acc[r][0] * ns; o.y = acc[r][1] * ns;
                o.z = acc[r][2] * ns; o.w = acc[r][3] * ns;
            }
            *(float4*)&Out[(size_t)gr * HID + tx * 4] = o;
        }
    }
}

// ---------------- 128-dim CSR gather aggregation + bias + relu ----------------
__global__ __launch_bounds__(256) void k_aggregate(const float* __restrict__ Hin,
                                                   const float* __restrict__ bias,
                                                   float* __restrict__ Hout) {
    int warp = (blockIdx.x * blockDim.x + threadIdx.x) >> 5;
    int lane = threadIdx.x & 31;
    if (warp >= NN) return;
    int beg = g_row_ptr[warp];
    int end = g_row_ptr[warp + 1];
    float4 acc0 = make_float4(0.f, 0.f, 0.f, 0.f);
    float4 acc1 = make_float4(0.f, 0.f, 0.f, 0.f);
    int e = beg;
    for (; e + 1 < end; e += 2) {   // 2-way ILP
        int s0 = g_csr_src[e];
        int s1 = g_csr_src[e + 1];
        float4 v0 = __ldg((const float4*)(Hin + (size_t)s0 * HID) + lane);
        float4 v1 = __ldg((const float4*)(Hin + (size_t)s1 * HID) + lane);
        acc0.x += v0.x; acc0.y += v0.y; acc0.z += v0.z; acc0.w += v0.w;
        acc1.x += v1.x; acc1.y += v1.y; acc1.z += v1.z; acc1.w += v1.w;
    }
    if (e < end) {
        int s0 = g_csr_src[e];
        float4 v0 = __ldg((const float4*)(Hin + (size_t)s0 * HID) + lane);
        acc0.x += v0.x; acc0.y += v0.y; acc0.z += v0.z; acc0.w += v0.w;
    }
    acc0.x += acc1.x; acc0.y += acc1.y; acc0.z += acc1.z; acc0.w += acc1.w;
    float nd = g_norm_dst[warp];
    float4 b = __ldg((const float4*)bias + lane);
    float4 o;
    o.x = fmaxf(acc0.x * nd + b.x, 0.f);
    o.y = fmaxf(acc0.y * nd + b.y, 0.f);
    o.z = fmaxf(acc0.z * nd + b.z, 0.f);
    o.w = fmaxf(acc0.w * nd + b.w, 0.f);
    ((float4*)(Hout + (size_t)warp * HID))[lane] = o;
}

// ---------------- per-batch exact top-K via register-blocked bitonic sort ------
// key = (float_bits(v) << 32) | (NPER - i): relu => v >= 0 => bits monotone;
// descending sort; larger low field = smaller index wins ties (lax.top_k).
// Padding keys = 0 sort to the tail (real low field >= 1).
#define CHUNK 16
extern __shared__ unsigned long long s_key[];   // SORT_M * 8 = 128 KB dynamic

__device__ __forceinline__ void local_ce(unsigned long long* v, int base, int k, int j) {
#pragma unroll
    for (int i = 0; i < CHUNK; i++) {
        int l = i ^ j;
        if (l > i) {
            bool desc = (((base + i) & k) == 0);
            unsigned long long a = v[i], c = v[l];
            if (desc ? (a < c) : (a > c)) { v[i] = c; v[l] = a; }
        }
    }
}

__global__ __launch_bounds__(1024) void k_sort(const float* __restrict__ H2) {
    int b = blockIdx.x;
    int t = threadIdx.x;
    int base = t * CHUNK;

    unsigned long long v[CHUNK];
#pragma unroll
    for (int q = 0; q < CHUNK; q++) {
        int i = base + q;
        unsigned long long key = 0ULL;
        if (i < NPER) {
            float val = H2[((size_t)(b * NPER + i)) * HID + 127] + 0.0f;  // -0 -> +0
            key = ((unsigned long long)__float_as_uint(val) << 32)
                  | (unsigned)(NPER - i);
        }
        v[q] = key;
    }
#pragma unroll
    for (int k = 2; k <= CHUNK; k <<= 1)
#pragma unroll
        for (int j = k >> 1; j >= 1; j >>= 1)
            local_ce(v, base, k, j);
#pragma unroll
    for (int q = 0; q < CHUNK; q++) s_key[base + q] = v[q];
    __syncthreads();

    for (int k = 32; k <= SORT_M; k <<= 1) {
        for (int j = k >> 1; j >= CHUNK; j >>= 1) {
#pragma unroll
            for (int q = 0; q < CHUNK; q++) {
                int i = base + q;
                int l = i ^ j;
                if (l > i) {
                    unsigned long long a = s_key[i];
                    unsigned long long c = s_key[l];
                    bool desc = ((i & k) == 0);
                    if (desc ? (a < c) : (a > c)) { s_key[i] = c; s_key[l] = a; }
                }
            }
            __syncthreads();
        }
#pragma unroll
        for (int q = 0; q < CHUNK; q++) v[q] = s_key[base + q];
#pragma unroll
        for (int j = CHUNK >> 1; j >= 1; j >>= 1)
            local_ce(v, base, k, j);
#pragma unroll
        for (int q = 0; q < CHUNK; q++) s_key[base + q] = v[q];
        __syncthreads();
    }

    for (int r = t; r < KSEL; r += 1024) {
        unsigned long long key = s_key[r];
        int i = NPER - (int)(key & 0xffffffffu);
        g_sel[b * KSEL + r] = b * NPER + i;
    }
}

// ---------------- output: smem-staged pooled @ W3 (deterministic) ----------------
// Block (x=chunk of 8 ranks, y=batch). Stage the 8 W3 slices (72 KB) + 8 H2
// rows (4 KB) in smem with coalesced float4 loads, then 144 threads each
// compute one (rank, class) dot product of length HID from smem.
#define FIN_SMEM ((RPB * HID * NCLS + RPB * HID) * (int)sizeof(float))  // 77824 B

extern __shared__ float s_fin[];   // [RPB*HID*NCLS] W slices, then [RPB*HID] x rows

__global__ __launch_bounds__(256) void k_final(const float* __restrict__ H2,
                                               const float* __restrict__ W3) {
    int b  = blockIdx.y;
    int t  = threadIdx.x;
    int r0 = blockIdx.x * RPB;

    float* sW = s_fin;                       // RPB*HID*NCLS floats
    float* sX = s_fin + RPB * HID * NCLS;    // RPB*HID floats

    // stage W3 slices: contiguous RPB*HID*NCLS floats starting at r0*HID*NCLS
    const float4* wsrc = (const float4*)(W3 + (size_t)r0 * HID * NCLS);
    const int WV = RPB * HID * NCLS / 4;     // 4608 float4
#pragma unroll
    for (int m = t; m < WV; m += 256)
        ((float4*)sW)[m] = __ldg(wsrc + m);

    // stage H2 rows: warp q loads rank r0+q's row (32 float4)
    {
        int q = t >> 5, lane = t & 31;
        int node = g_sel[b * KSEL + r0 + q];
        ((float4*)sX)[q * (HID / 4) + lane] =
            __ldg((const float4*)(H2 + (size_t)node * HID) + lane);
    }
    __syncthreads();

    // compute: thread (q, c) for t < RPB*NCLS = 144
    __shared__ float red[RPB * NCLS];
    if (t < RPB * NCLS) {
        int q = t / NCLS, c = t % NCLS;
        const float* x = sX + q * HID;
        const float* w = sW + q * HID * NCLS + c;
        float acc = 0.f;
#pragma unroll 8
        for (int h = 0; h < HID; h++)
            acc += x[h] * w[h * NCLS];
        red[t] = acc;
    }
    __syncthreads();

    // fixed-order sum over the 8 ranks of this block
    if (t < NCLS) {
        float s = 0.f;
#pragma unroll
        for (int q = 0; q < RPB; q++) s += red[q * NCLS + t];
        g_partial[((size_t)b * FIN_BLK + blockIdx.x) * NCLS + t] = s;
    }
}

// warp-per-output reduction: 18 blocks x 256 threads = 144 warps = BATCH*NCLS
__global__ __launch_bounds__(256) void k_reduce(const float* __restrict__ b3,
                                                float* __restrict__ out) {
    int w    = blockIdx.x * 8 + (threadIdx.x >> 5);   // output index 0..143
    int lane = threadIdx.x & 31;
    if (w >= BATCH * NCLS) return;
    int b = w / NCLS, c = w % NCLS;
    float s = 0.f;
    for (int blk = lane; blk < FIN_BLK; blk += 32)    // fixed per-lane order
        s += g_partial[((size_t)b * FIN_BLK + blk) * NCLS + c];
#pragma unroll
    for (int off = 16; off > 0; off >>= 1)            // fixed-tree reduce
        s += __shfl_down_sync(0xffffffffu, s, off);
    if (lane == 0) out[w] = s + __ldg(&b3[c]);
}

// ---------------- launch ----------------
extern "C" void kernel_launch(void* const* d_in, const int* in_sizes, int n_in,
                              void* d_out, int out_size) {
    const float* features = (const float*)d_in[0];
    const int*   src      = (const int*)  d_in[1];
    const int*   dst      = (const int*)  d_in[2];
    const float* W1       = (const float*)d_in[3];
    const float* b1       = (const float*)d_in[4];
    const float* W2       = (const float*)d_in[5];
    const float* b2       = (const float*)d_in[6];
    const float* W3       = (const float*)d_in[7];
    const float* b3       = (const float*)d_in[8];
    float* out = (float*)d_out;

    float *bufA, *bufB;
    cudaGetSymbolAddress((void**)&bufA, g_bufA);
    cudaGetSymbolAddress((void**)&bufB, g_bufB);

    // opt-in to large dynamic smem (attribute set, not a stream op: safe under
    // graph capture; idempotent across calls)
    cudaFuncSetAttribute(k_sort, cudaFuncAttributeMaxDynamicSharedMemorySize,
                         SORT_M * (int)sizeof(unsigned long long));
    cudaFuncSetAttribute(k_final, cudaFuncAttributeMaxDynamicSharedMemorySize,
                         FIN_SMEM);

    // 1) degrees + norms
    k_zero_deg<<<(NN + 255) / 256, 256>>>();
    k_degrees<<<(EE + 255) / 256, 256>>>(src, dst);
    k_norms<<<(NN + 255) / 256, 256>>>();

    // 2) CSR by dst
    k_scan<<<1, 1024>>>();
    k_csr_scatter<<<(EE + 255) / 256, 256>>>(src, dst);

    // 3) layer 1 (aggregate in 64-dim with fused src-norm, then transform —
    //    algebraically equal to reference, halves gather traffic)
    k_agg64<<<(NN * 32 + 255) / 256, 256>>>(features, bufB);         // bufB = 64-dim agg
    k_gemm<IN_DIM, 1><<<(NN + 63) / 64, 256>>>(bufB, W1, b1, bufA);  // bufA = h1

    // 4) layer 2: transform+ns, gather-aggregate + relu(acc*nd + b2)
    k_gemm<HID, 0><<<(NN + 63) / 64, 256>>>(bufA, W2, nullptr, bufB);
    k_aggregate<<<(NN * 32 + 255) / 256, 256>>>(bufB, b2, bufA);     // bufA = h2

    // 5) exact per-batch top-K (register-blocked bitonic sort, 1 block/batch)
    k_sort<<<BATCH, 1024, SORT_M * sizeof(unsigned long long)>>>(bufA);

    // 6) pooled @ W3 + b3 (smem-staged, deterministic two-stage reduction)
    {
        dim3 grid(FIN_BLK, BATCH);   // (625, 8)
        k_final<<<grid, 256, FIN_SMEM>>>(bufA, W3);
    }
    k_reduce<<<18, 256>>>(b3, out);
}

// round 9
// speedup vs baseline: 1.1369x; 1.1369x over previous
#include <cuda_runtime.h>
#include <cuda_bf16.h>
#include <cstdint>

// Problem constants
#define NN      100000
#define EE      1600000
#define IN_DIM  64
#define HID     128
#define NCLS    18
#define BATCH   8
#define KSEL    5000
#define NPER    (NN / BATCH)   // 12500
#define SORT_M  16384          // next pow2 >= NPER
#define RPB     8              // ranks per block in k_final
#define FIN_BLK (KSEL / RPB)   // 625 rank-chunks
#define SCAN_B  256
#define SCAN_G  ((NN + SCAN_B - 1) / SCAN_B)   // 391

// ---------------- scratch (static device globals; no allocation) ----------------
__device__ float g_bufA[(size_t)NN * HID];   // 51.2 MB
__device__ float g_bufB[(size_t)NN * HID];   // 51.2 MB
__device__ int   g_out_deg[NN];
__device__ int   g_in_deg[NN];
__device__ float g_norm_src[NN];
__device__ float g_norm_dst[NN];
__device__ int   g_row_ptr[NN + 1];
__device__ int   g_pos[NN];
__device__ int   g_csr_src[EE];
__device__ int   g_blk[SCAN_G];
__device__ int   g_sel[BATCH * KSEL];                    // sel[b*K + rank] = global node id
__device__ float g_partial[BATCH * FIN_BLK * NCLS];      // deterministic reduction staging

// ---------------- degree / norm ----------------
__global__ void k_zero_deg() {
    int i = blockIdx.x * blockDim.x + threadIdx.x;
    if (i < NN) { g_out_deg[i] = 0; g_in_deg[i] = 0; }
}

__global__ void k_degrees(const int* __restrict__ src, const int* __restrict__ dst) {
    int e = blockIdx.x * blockDim.x + threadIdx.x;
    if (e < EE) {
        atomicAdd(&g_out_deg[src[e]], 1);
        atomicAdd(&g_in_deg[dst[e]], 1);
    }
}

__global__ void k_norms() {
    int i = blockIdx.x * blockDim.x + threadIdx.x;
    if (i < NN) {
        int od = g_out_deg[i]; if (od < 1) od = 1;
        int id = g_in_deg[i];  if (id < 1) id = 1;
        g_norm_src[i] = rsqrtf((float)od);
        g_norm_dst[i] = rsqrtf((float)id);
    }
}

// ---------------- CSR build: parallel 3-pass exclusive scan of in_deg ----------
__global__ __launch_bounds__(SCAN_B) void k_scan_a() {
    __shared__ int sh[SCAN_B];
    int t = threadIdx.x;
    int i = blockIdx.x * SCAN_B + t;
    sh[t] = (i < NN) ? g_in_deg[i] : 0;
    __syncthreads();
    for (int s = SCAN_B / 2; s > 0; s >>= 1) {
        if (t < s) sh[t] += sh[t + s];
        __syncthreads();
    }
    if (t == 0) g_blk[blockIdx.x] = sh[0];
}

__global__ __launch_bounds__(512) void k_scan_b() {
    __shared__ int sm[512];
    int t = threadIdx.x;
    sm[t] = (t < SCAN_G) ? g_blk[t] : 0;
    __syncthreads();
    for (int off = 1; off < 512; off <<= 1) {
        int v = (t >= off) ? sm[t - off] : 0;
        __syncthreads();
        sm[t] += v;
        __syncthreads();
    }
    if (t < SCAN_G) g_blk[t] = (t == 0) ? 0 : sm[t - 1];
    if (t == SCAN_G - 1) g_row_ptr[NN] = sm[t];   // == EE
}

__global__ __launch_bounds__(SCAN_B) void k_scan_c() {
    __shared__ int sm[SCAN_B];
    int t = threadIdx.x;
    int i = blockIdx.x * SCAN_B + t;
    int v = (i < NN) ? g_in_deg[i] : 0;
    sm[t] = v;
    __syncthreads();
    for (int off = 1; off < SCAN_B; off <<= 1) {
        int u = (t >= off) ? sm[t - off] : 0;
        __syncthreads();
        sm[t] += u;
        __syncthreads();
    }
    if (i < NN) {
        int excl = g_blk[blockIdx.x] + sm[t] - v;
        g_row_ptr[i] = excl;
        g_pos[i]     = excl;
    }
}

__global__ void k_csr_scatter(const int* __restrict__ src, const int* __restrict__ dst) {
    int e = blockIdx.x * blockDim.x + threadIdx.x;
    if (e < EE) {
        int p = atomicAdd(&g_pos[dst[e]], 1);
        g_csr_src[p] = src[e];
    }
}

// ---------------- 64-dim CSR gather aggregation with fused src-norm ----------
// Hout[v,:] = sum_{e: dst==v} X[csr_src[e],:] * norm_src[csr_src[e]]
__global__ __launch_bounds__(256) void k_agg64(const float* __restrict__ X,
                                               float* __restrict__ Hout) {
    int warp = (blockIdx.x * blockDim.x + threadIdx.x) >> 5;
    int lane = threadIdx.x & 31;
    if (warp >= NN) return;
    int beg = g_row_ptr[warp];
    int end = g_row_ptr[warp + 1];
    float2 a0 = make_float2(0.f, 0.f), a1 = make_float2(0.f, 0.f);
    float2 a2 = make_float2(0.f, 0.f), a3 = make_float2(0.f, 0.f);
    int e = beg;
    for (; e + 3 < end; e += 4) {   // 4-way MLP
        int s0 = g_csr_src[e],     s1 = g_csr_src[e + 1];
        int s2 = g_csr_src[e + 2], s3 = g_csr_src[e + 3];
        float n0 = __ldg(&g_norm_src[s0]), n1 = __ldg(&g_norm_src[s1]);
        float n2 = __ldg(&g_norm_src[s2]), n3 = __ldg(&g_norm_src[s3]);
        float2 v0 = __ldg((const float2*)(X + (size_t)s0 * IN_DIM) + lane);
        float2 v1 = __ldg((const float2*)(X + (size_t)s1 * IN_DIM) + lane);
        float2 v2 = __ldg((const float2*)(X + (size_t)s2 * IN_DIM) + lane);
        float2 v3 = __ldg((const float2*)(X + (size_t)s3 * IN_DIM) + lane);
        a0.x += v0.x * n0; a0.y += v0.y * n0;
        a1.x += v1.x * n1; a1.y += v1.y * n1;
        a2.x += v2.x * n2; a2.y += v2.y * n2;
        a3.x += v3.x * n3; a3.y += v3.y * n3;
    }
    for (; e < end; e++) {
        int s0 = g_csr_src[e];
        float n0 = __ldg(&g_norm_src[s0]);
        float2 v0 = __ldg((const float2*)(X + (size_t)s0 * IN_DIM) + lane);
        a0.x += v0.x * n0; a0.y += v0.y * n0;
    }
    a0.x += a1.x; a0.y += a1.y;
    a2.x += a3.x; a2.y += a3.y;
    a0.x += a2.x; a0.y += a2.y;
    ((float2*)(Hout + (size_t)warp * IN_DIM))[lane] = a0;
}

// ---------------- dense transform ----------------
// POST=1: Out[i,:] = relu((A[i,:KD] @ W) * norm_dst[i] + bias)   (layer-1 tail)
// POST=0: Out[i,:] = (A[i,:KD] @ W) * norm_src[i]                (layer-2 head)
template <int KD, int POST>
__global__ __launch_bounds__(256) void k_gemm(const float* __restrict__ A,
                                              const float* __restrict__ W,
                                              const float* __restrict__ bias,
                                              float* __restrict__ Out) {
    const int TM = 64;
    __shared__ float As[TM][32];      // 8 KB
    __shared__ float Bs[32][HID];     // 16 KB
    int t  = threadIdx.x;
    int tx = t & 31;                  // col group: cols tx*4 .. tx*4+3
    int ty = t >> 5;                  // row group: rows ty*8 .. ty*8+7
    int row0 = blockIdx.x * TM;

    float acc[8][4];
#pragma unroll
    for (int r = 0; r < 8; r++)
#pragma unroll
        for (int c = 0; c < 4; c++) acc[r][c] = 0.f;

    for (int kk = 0; kk < KD; kk += 32) {
#pragma unroll
        for (int j = 0; j < 8; j++) {      // 2048 elems of As
            int m = t + j * 256;
            int r = m >> 5, c = m & 31;
            int gr = row0 + r;
            As[r][c] = (gr < NN) ? A[(size_t)gr * KD + kk + c] : 0.f;
        }
#pragma unroll
        for (int j = 0; j < 16; j++) {     // 4096 elems of Bs
            int m = t + j * 256;
            int r = m >> 7, c = m & 127;
            Bs[r][c] = W[(size_t)(kk + r) * HID + c];
        }
        __syncthreads();
#pragma unroll
        for (int k4 = 0; k4 < 8; k4++) {   // 4 K-steps per iter, float4 As reads
            float4 b0 = *(const float4*)&Bs[k4 * 4 + 0][tx * 4];
            float4 b1 = *(const float4*)&Bs[k4 * 4 + 1][tx * 4];
            float4 b2 = *(const float4*)&Bs[k4 * 4 + 2][tx * 4];
            float4 b3 = *(const float4*)&Bs[k4 * 4 + 3][tx * 4];
#pragma unroll
            for (int r = 0; r < 8; r++) {
                float4 a = *(const float4*)&As[ty * 8 + r][k4 * 4];
                acc[r][0] += a.x * b0.x + a.y * b1.x + a.z * b2.x + a.w * b3.x;
                acc[r][1] += a.x * b0.y + a.y * b1.y + a.z * b2.y + a.w * b3.y;
                acc[r][2] += a.x * b0.z + a.y * b1.z + a.z * b2.z + a.w * b3.z;
                acc[r][3] += a.x * b0.w + a.y * b1.w + a.z * b2.w + a.w * b3.w;
            }
        }
        __syncthreads();
    }
#pragma unroll
    for (int r = 0; r < 8; r++) {
        int gr = row0 + ty * 8 + r;
        if (gr < NN) {
            float4 o;
            if (POST) {
                float nd = g_norm_dst[gr];
                float4 b = __ldg((const float4*)bias + tx);
                o.x = fmaxf(acc[r][0] * nd + b.x, 0.f);
                o.y = fmaxf(acc[r][1] * nd + b.y, 0.f);
                o.z = fmaxf(acc[r][2] * nd + b.z, 0.f);
                o.w = fmaxf(acc[r][3] * nd + b.w, 0.f);
            } else {
                float ns = g_norm_src[gr];
                o.x = acc[r][0] * ns; o.y = acc[r][1] * ns;
                o.z = acc[r][2] * ns; o.w = acc[r][3] * ns;
            }
            *(float4*)&Out[(size_t)gr * HID + tx * 4] = o;
        }
    }
}

// ---------------- 128-dim CSR gather aggregation + bias + relu ----------------
__global__ __launch_bounds__(256) void k_aggregate(const float* __restrict__ Hin,
                                                   const float* __restrict__ bias,
                                                   float* __restrict__ Hout) {
    int warp = (blockIdx.x * blockDim.x + threadIdx.x) >> 5;
    int lane = threadIdx.x & 31;
    if (warp >= NN) return;
    int beg = g_row_ptr[warp];
    int end = g_row_ptr[warp + 1];
    float4 a0 = make_float4(0.f, 0.f, 0.f, 0.f);
    float4 a1 = make_float4(0.f, 0.f, 0.f, 0.f);
    float4 a2 = make_float4(0.f, 0.f, 0.f, 0.f);
    float4 a3 = make_float4(0.f, 0.f, 0.f, 0.f);
    int e = beg;
    for (; e + 3 < end; e += 4) {   // 4-way MLP
        int s0 = g_csr_src[e],     s1 = g_csr_src[e + 1];
        int s2 = g_csr_src[e + 2], s3 = g_csr_src[e + 3];
        float4 v0 = __ldg((const float4*)(Hin + (size_t)s0 * HID) + lane);
        float4 v1 = __ldg((const float4*)(Hin + (size_t)s1 * HID) + lane);
        float4 v2 = __ldg((const float4*)(Hin + (size_t)s2 * HID) + lane);
        float4 v3 = __ldg((const float4*)(Hin + (size_t)s3 * HID) + lane);
        a0.x += v0.x; a0.y += v0.y; a0.z += v0.z; a0.w += v0.w;
        a1.x += v1.x; a1.y += v1.y; a1.z += v1.z; a1.w += v1.w;
        a2.x += v2.x; a2.y += v2.y; a2.z += v2.z; a2.w += v2.w;
        a3.x += v3.x; a3.y += v3.y; a3.z += v3.z; a3.w += v3.w;
    }
    for (; e < end; e++) {
        int s0 = g_csr_src[e];
        float4 v0 = __ldg((const float4*)(Hin + (size_t)s0 * HID) + lane);
        a0.x += v0.x; a0.y += v0.y; a0.z += v0.z; a0.w += v0.w;
    }
    a0.x += a1.x; a0.y += a1.y; a0.z += a1.z; a0.w += a1.w;
    a2.x += a3.x; a2.y += a3.y; a2.z += a3.z; a2.w += a3.w;
    a0.x += a2.x; a0.y += a2.y; a0.z += a2.z; a0.w += a2.w;
    float nd = g_norm_dst[warp];
    float4 b = __ldg((const float4*)bias + lane);
    float4 o;
    o.x = fmaxf(a0.x * nd + b.x, 0.f);
    o.y = fmaxf(a0.y * nd + b.y, 0.f);
    o.z = fmaxf(a0.z * nd + b.z, 0.f);
    o.w = fmaxf(a0.w * nd + b.w, 0.f);
    ((float4*)(Hout + (size_t)warp * HID))[lane] = o;
}

// ---------------- per-batch exact top-K via register-blocked bitonic sort ------
// key = (float_bits(v) << 32) | (NPER - i): relu => v >= 0 => bits monotone;
// descending sort; larger low field = smaller index wins ties (lax.top_k).
// Padding keys = 0 sort to the tail (real low field >= 1).
#define CHUNK 16
extern __shared__ unsigned long long s_key[];   // SORT_M * 8 = 128 KB dynamic

__device__ __forceinline__ void local_ce(unsigned long long* v, int base, int k, int j) {
#pragma unroll
    for (int i = 0; i < CHUNK; i++) {
        int l = i ^ j;
        if (l > i) {
            bool desc = (((base + i) & k) == 0);
            unsigned long long a = v[i], c = v[l];
            if (desc ? (a < c) : (a > c)) { v[i] = c; v[l] = a; }
        }
    }
}

__global__ __launch_bounds__(1024) void k_sort(const float* __restrict__ H2) {
    int b = blockIdx.x;
    int t = threadIdx.x;
    int base = t * CHUNK;

    unsigned long long v[CHUNK];
#pragma unroll
    for (int q = 0; q < CHUNK; q++) {
        int i = base + q;
        unsigned long long key = 0ULL;
        if (i < NPER) {
            float val = H2[((size_t)(b * NPER + i)) * HID + 127] + 0.0f;  // -0 -> +0
            key = ((unsigned long long)__float_as_uint(val) << 32)
                  | (unsigned)(NPER - i);
        }
        v[q] = key;
    }
#pragma unroll
    for (int k = 2; k <= CHUNK; k <<= 1)
#pragma unroll
        for (int j = k >> 1; j >= 1; j >>= 1)
            local_ce(v, base, k, j);
#pragma unroll
    for (int q = 0; q < CHUNK; q++) s_key[base + q] = v[q];
    __syncthreads();

    for (int k = 32; k <= SORT_M; k <<= 1) {
        for (int j = k >> 1; j >= CHUNK; j >>= 1) {
#pragma unroll
            for (int q = 0; q < CHUNK; q++) {
                int i = base + q;
                int l = i ^ j;
                if (l > i) {
                    unsigned long long a = s_key[i];
                    unsigned long long c = s_key[l];
                    bool desc = ((i & k) == 0);
                    if (desc ? (a < c) : (a > c)) { s_key[i] = c; s_key[l] = a; }
                }
            }
            __syncthreads();
        }
#pragma unroll
        for (int q = 0; q < CHUNK; q++) v[q] = s_key[base + q];
#pragma unroll
        for (int j = CHUNK >> 1; j >= 1; j >>= 1)
            local_ce(v, base, k, j);
#pragma unroll
        for (int q = 0; q < CHUNK; q++) s_key[base + q] = v[q];
        __syncthreads();
    }

    for (int r = t; r < KSEL; r += 1024) {
        unsigned long long key = s_key[r];
        int i = NPER - (int)(key & 0xffffffffu);
        g_sel[b * KSEL + r] = b * NPER + i;
    }
}

// ---------------- output: smem-staged pooled @ W3, W3 reused across batches ----
#define FIN_SMEM ((RPB * HID * NCLS + BATCH * RPB * HID) * (int)sizeof(float))  // 106496 B

extern __shared__ float s_fin[];   // [RPB*HID*NCLS] W slice, then [BATCH*RPB*HID] rows

__global__ __launch_bounds__(256) void k_final(const float* __restrict__ H2,
                                               const float* __restrict__ W3) {
    int t  = threadIdx.x;
    int r0 = blockIdx.x * RPB;

    float* sW = s_fin;                        // RPB*HID*NCLS floats
    float* sX = s_fin + RPB * HID * NCLS;     // BATCH*RPB*HID floats

    const float4* wsrc = (const float4*)(W3 + (size_t)r0 * HID * NCLS);
    const int WV = RPB * HID * NCLS / 4;      // 4608 float4
    for (int m = t; m < WV; m += 256)
        ((float4*)sW)[m] = __ldg(wsrc + m);

    {
        int warp = t >> 5, lane = t & 31;
        for (int p = warp; p < BATCH * RPB; p += 8) {
            int b = p >> 3, q = p & 7;
            int node = g_sel[b * KSEL + r0 + q];
            ((float4*)sX)[p * (HID / 4) + lane] =
                __ldg((const float4*)(H2 + (size_t)node * HID) + lane);
        }
    }
    __syncthreads();

    __shared__ float red[RPB * NCLS];
    for (int b = 0; b < BATCH; b++) {
        if (t < RPB * NCLS) {
            int q = t / NCLS, c = t % NCLS;
            const float* x = sX + (b * RPB + q) * HID;
            const float* w = sW + q * HID * NCLS + c;
            float acc = 0.f;
#pragma unroll 8
            for (int h = 0; h < HID; h++)
                acc += x[h] * w[h * NCLS];
            red[t] = acc;
        }
        __syncthreads();
        if (t < NCLS) {
            float s = 0.f;
#pragma unroll
            for (int q = 0; q < RPB; q++) s += red[q * NCLS + t];
            g_partial[((size_t)b * FIN_BLK + blockIdx.x) * NCLS + t] = s;
        }
        __syncthreads();
    }
}

// warp-per-output reduction: 18 blocks x 256 threads = 144 warps = BATCH*NCLS
__global__ __launch_bounds__(256) void k_reduce(const float* __restrict__ b3,
                                                float* __restrict__ out) {
    int w    = blockIdx.x * 8 + (threadIdx.x >> 5);   // output index 0..143
    int lane = threadIdx.x & 31;
    if (w >= BATCH * NCLS) return;
    int b = w / NCLS, c = w % NCLS;
    float s = 0.f;
    for (int blk = lane; blk < FIN_BLK; blk += 32)    // fixed per-lane order
        s += g_partial[((size_t)b * FIN_BLK + blk) * NCLS + c];
#pragma unroll
    for (int off = 16; off > 0; off >>= 1)            // fixed-tree reduce
        s += __shfl_down_sync(0xffffffffu, s, off);
    if (lane == 0) out[w] = s + __ldg(&b3[c]);
}

// ---------------- launch ----------------
extern "C" void kernel_launch(void* const* d_in, const int* in_sizes, int n_in,
                              void* d_out, int out_size) {
    const float* features = (const float*)d_in[0];
    const int*   src      = (const int*)  d_in[1];
    const int*   dst      = (const int*)  d_in[2];
    const float* W1       = (const float*)d_in[3];
    const float* b1       = (const float*)d_in[4];
    const float* W2       = (const float*)d_in[5];
    const float* b2       = (const float*)d_in[6];
    const float* W3       = (const float*)d_in[7];
    const float* b3       = (const float*)d_in[8];
    float* out = (float*)d_out;

    float *bufA, *bufB;
    cudaGetSymbolAddress((void**)&bufA, g_bufA);
    cudaGetSymbolAddress((void**)&bufB, g_bufB);

    cudaFuncSetAttribute(k_sort, cudaFuncAttributeMaxDynamicSharedMemorySize,
                         SORT_M * (int)sizeof(unsigned long long));
    cudaFuncSetAttribute(k_final, cudaFuncAttributeMaxDynamicSharedMemorySize,
                         FIN_SMEM);

    // 1) degrees + norms
    k_zero_deg<<<(NN + 255) / 256, 256>>>();
    k_degrees<<<(EE + 255) / 256, 256>>>(src, dst);
    k_norms<<<(NN + 255) / 256, 256>>>();

    // 2) CSR by dst (parallel 3-pass scan, then scatter)
    k_scan_a<<<SCAN_G, SCAN_B>>>();
    k_scan_b<<<1, 512>>>();
    k_scan_c<<<SCAN_G, SCAN_B>>>();
    k_csr_scatter<<<(EE + 255) / 256, 256>>>(src, dst);

    // 3) layer 1 (aggregate in 64-dim with fused src-norm, then transform)
    k_agg64<<<(NN * 32 + 255) / 256, 256>>>(features, bufB);
    k_gemm<IN_DIM, 1><<<(NN + 63) / 64, 256>>>(bufB, W1, b1, bufA);  // bufA = h1

    // 4) layer 2: transform+ns, gather-aggregate + relu(acc*nd + b2)
    k_gemm<HID, 0><<<(NN + 63) / 64, 256>>>(bufA, W2, nullptr, bufB);
    k_aggregate<<<(NN * 32 + 255) / 256, 256>>>(bufB, b2, bufA);     // bufA = h2

    // 5) exact per-batch top-K (register-blocked bitonic sort, 1 block/batch)
    k_sort<<<BATCH, 1024, SORT_M * sizeof(unsigned long long)>>>(bufA);

    // 6) pooled @ W3 + b3 (W3 slice shared across all batches; deterministic)
    k_final<<<FIN_BLK, 256, FIN_SMEM>>>(bufA, W3);
    k_reduce<<<18, 256>>>(b3, out);
}

// round 13
// speedup vs baseline: 2.2542x; 1.9827x over previous
#include <cuda_runtime.h>
#include <cuda_bf16.h>
#include <cstdint>

// Problem constants
#define NN      100000
#define EE      1600000
#define IN_DIM  64
#define HID     128
#define NCLS    18
#define BATCH   8
#define KSEL    5000
#define NPER    (NN / BATCH)   // 12500
#define SORT_M  16384          // next pow2 >= NPER
#define RPB     8              // ranks per block in k_final
#define FIN_BLK (KSEL / RPB)   // 625 rank-chunks
#define SCAN_B  256
#define SCAN_G  ((NN + SCAN_B - 1) / SCAN_B)   // 391

// ---------------- scratch (static device globals; no allocation) ----------------
__device__ float g_bufA[(size_t)NN * HID];   // 51.2 MB
__device__ float g_bufB[(size_t)NN * HID];   // 51.2 MB
__device__ int   g_out_deg[NN];
__device__ int   g_in_deg[NN];
__device__ float g_norm_src[NN];
__device__ float g_norm_dst[NN];
__device__ int   g_row_ptr[NN + 1];
__device__ int   g_pos[NN];
__device__ int   g_csr_src[EE];
__device__ int   g_blk[SCAN_G];
__device__ int   g_sel[BATCH * KSEL];                    // sel[b*K + rank] = global node id
__device__ float g_partial[BATCH * FIN_BLK * NCLS];      // deterministic reduction staging

// ---------------- degree / norm ----------------
__global__ void k_zero_deg() {
    int i = blockIdx.x * blockDim.x + threadIdx.x;
    if (i < NN) { g_out_deg[i] = 0; g_in_deg[i] = 0; }
}

__global__ void k_degrees(const int* __restrict__ src, const int* __restrict__ dst) {
    int e = blockIdx.x * blockDim.x + threadIdx.x;
    if (e < EE) {
        atomicAdd(&g_out_deg[src[e]], 1);
        atomicAdd(&g_in_deg[dst[e]], 1);
    }
}

__global__ void k_norms() {
    int i = blockIdx.x * blockDim.x + threadIdx.x;
    if (i < NN) {
        int od = g_out_deg[i]; if (od < 1) od = 1;
        int id = g_in_deg[i];  if (id < 1) id = 1;
        g_norm_src[i] = rsqrtf((float)od);
        g_norm_dst[i] = rsqrtf((float)id);
    }
}

// ---------------- CSR build: parallel 3-pass exclusive scan of in_deg ----------
__global__ __launch_bounds__(SCAN_B) void k_scan_a() {
    __shared__ int sh[SCAN_B];
    int t = threadIdx.x;
    int i = blockIdx.x * SCAN_B + t;
    sh[t] = (i < NN) ? g_in_deg[i] : 0;
    __syncthreads();
    for (int s = SCAN_B / 2; s > 0; s >>= 1) {
        if (t < s) sh[t] += sh[t + s];
        __syncthreads();
    }
    if (t == 0) g_blk[blockIdx.x] = sh[0];
}

__global__ __launch_bounds__(512) void k_scan_b() {
    __shared__ int sm[512];
    int t = threadIdx.x;
    sm[t] = (t < SCAN_G) ? g_blk[t] : 0;
    __syncthreads();
    for (int off = 1; off < 512; off <<= 1) {
        int v = (t >= off) ? sm[t - off] : 0;
        __syncthreads();
        sm[t] += v;
        __syncthreads();
    }
    if (t < SCAN_G) g_blk[t] = (t == 0) ? 0 : sm[t - 1];
    if (t == SCAN_G - 1) g_row_ptr[NN] = sm[t];   // == EE
}

__global__ __launch_bounds__(SCAN_B) void k_scan_c() {
    __shared__ int sm[SCAN_B];
    int t = threadIdx.x;
    int i = blockIdx.x * SCAN_B + t;
    int v = (i < NN) ? g_in_deg[i] : 0;
    sm[t] = v;
    __syncthreads();
    for (int off = 1; off < SCAN_B; off <<= 1) {
        int u = (t >= off) ? sm[t - off] : 0;
        __syncthreads();
        sm[t] += u;
        __syncthreads();
    }
    if (i < NN) {
        int excl = g_blk[blockIdx.x] + sm[t] - v;
        g_row_ptr[i] = excl;
        g_pos[i]     = excl;
    }
}

__global__ void k_csr_scatter(const int* __restrict__ src, const int* __restrict__ dst) {
    int e = blockIdx.x * blockDim.x + threadIdx.x;
    if (e < EE) {
        int p = atomicAdd(&g_pos[dst[e]], 1);
        g_csr_src[p] = src[e];
    }
}

// ---------------- 64-dim CSR gather aggregation with fused src-norm ----------
// Hout[v,:] = sum_{e: dst==v} X[csr_src[e],:] * norm_src[csr_src[e]]
__global__ __launch_bounds__(256) void k_agg64(const float* __restrict__ X,
                                               float* __restrict__ Hout) {
    int warp = (blockIdx.x * blockDim.x + threadIdx.x) >> 5;
    int lane = threadIdx.x & 31;
    if (warp >= NN) return;
    int beg = g_row_ptr[warp];
    int end = g_row_ptr[warp + 1];
    float2 a0 = make_float2(0.f, 0.f), a1 = make_float2(0.f, 0.f);
    float2 a2 = make_float2(0.f, 0.f), a3 = make_float2(0.f, 0.f);
    int e = beg;
    for (; e + 3 < end; e += 4) {   // 4-way MLP
        int s0 = g_csr_src[e],     s1 = g_csr_src[e + 1];
        int s2 = g_csr_src[e + 2], s3 = g_csr_src[e + 3];
        float n0 = __ldg(&g_norm_src[s0]), n1 = __ldg(&g_norm_src[s1]);
        float n2 = __ldg(&g_norm_src[s2]), n3 = __ldg(&g_norm_src[s3]);
        float2 v0 = __ldg((const float2*)(X + (size_t)s0 * IN_DIM) + lane);
        float2 v1 = __ldg((const float2*)(X + (size_t)s1 * IN_DIM) + lane);
        float2 v2 = __ldg((const float2*)(X + (size_t)s2 * IN_DIM) + lane);
        float2 v3 = __ldg((const float2*)(X + (size_t)s3 * IN_DIM) + lane);
        a0.x += v0.x * n0; a0.y += v0.y * n0;
        a1.x += v1.x * n1; a1.y += v1.y * n1;
        a2.x += v2.x * n2; a2.y += v2.y * n2;
        a3.x += v3.x * n3; a3.y += v3.y * n3;
    }
    for (; e < end; e++) {
        int s0 = g_csr_src[e];
        float n0 = __ldg(&g_norm_src[s0]);
        float2 v0 = __ldg((const float2*)(X + (size_t)s0 * IN_DIM) + lane);
        a0.x += v0.x * n0; a0.y += v0.y * n0;
    }
    a0.x += a1.x; a0.y += a1.y;
    a2.x += a3.x; a2.y += a3.y;
    a0.x += a2.x; a0.y += a2.y;
    ((float2*)(Hout + (size_t)warp * IN_DIM))[lane] = a0;
}

// ---------------- dense transform ----------------
// POST=1: Out[i,:] = relu((A[i,:KD] @ W) * norm_dst[i] + bias)   (layer-1 tail)
// POST=0: Out[i,:] = (A[i,:KD] @ W) * norm_src[i]                (layer-2 head)
template <int KD, int POST>
__global__ __launch_bounds__(256) void k_gemm(const float* __restrict__ A,
                                              const float* __restrict__ W,
                                              const float* __restrict__ bias,
                                              float* __restrict__ Out) {
    const int TM = 64;
    __shared__ float As[TM][32];      // 8 KB
    __shared__ float Bs[32][HID];     // 16 KB
    int t  = threadIdx.x;
    int tx = t & 31;                  // col group: cols tx*4 .. tx*4+3
    int ty = t >> 5;                  // row group: rows ty*8 .. ty*8+7
    int row0 = blockIdx.x * TM;

    float acc[8][4];
#pragma unroll
    for (int r = 0; r < 8; r++)
#pragma unroll
        for (int c = 0; c < 4; c++) acc[r][c] = 0.f;

    for (int kk = 0; kk < KD; kk += 32) {
#pragma unroll
        for (int j = 0; j < 8; j++) {      // 2048 elems of As
            int m = t + j * 256;
            int r = m >> 5, c = m & 31;
            int gr = row0 + r;
            As[r][c] = (gr < NN) ? A[(size_t)gr * KD + kk + c] : 0.f;
        }
#pragma unroll
        for (int j = 0; j < 16; j++) {     // 4096 elems of Bs
            int m = t + j * 256;
            int r = m >> 7, c = m & 127;
            Bs[r][c] = W[(size_t)(kk + r) * HID + c];
        }
        __syncthreads();
#pragma unroll
        for (int k4 = 0; k4 < 8; k4++) {   // 4 K-steps per iter, float4 As reads
            float4 b0 = *(const float4*)&Bs[k4 * 4 + 0][tx * 4];
            float4 b1 = *(const float4*)&Bs[k4 * 4 + 1][tx * 4];
            float4 b2 = *(const float4*)&Bs[k4 * 4 + 2][tx * 4];
            float4 b3 = *(const float4*)&Bs[k4 * 4 + 3][tx * 4];
#pragma unroll
            for (int r = 0; r < 8; r++) {
                float4 a = *(const float4*)&As[ty * 8 + r][k4 * 4];
                acc[r][0] += a.x * b0.x + a.y * b1.x + a.z * b2.x + a.w * b3.x;
                acc[r][1] += a.x * b0.y + a.y * b1.y + a.z * b2.y + a.w * b3.y;
                acc[r][2] += a.x * b0.z + a.y * b1.z + a.z * b2.z + a.w * b3.z;
                acc[r][3] += a.x * b0.w + a.y * b1.w + a.z * b2.w + a.w * b3.w;
            }
        }
        __syncthreads();
    }
#pragma unroll
    for (int r = 0; r < 8; r++) {
        int gr = row0 + ty * 8 + r;
        if (gr < NN) {
            float4 o;
            if (POST) {
                float nd = g_norm_dst[gr];
                float4 b = __ldg((const float4*)bias + tx);
                o.x = fmaxf(acc[r][0] * nd + b.x, 0.f);
                o.y = fmaxf(acc[r][1] * nd + b.y, 0.f);
                o.z = fmaxf(acc[r][2] * nd + b.z, 0.f);
                o.w = fmaxf(acc[r][3] * nd + b.w, 0.f);
            } else {
                float ns = g_norm_src[gr];
                o.x = acc[r][0] * ns; o.y = acc[r][1] * ns;
                o.z = acc[r][2] * ns; o.w = acc[r][3] * ns;
            }
            *(float4*)&Out[(size_t)gr * HID + tx * 4] = o;
        }
    }
}

// ---------------- 128-dim CSR gather aggregation + bias + relu ----------------
__global__ __launch_bounds__(256) void k_aggregate(const float* __restrict__ Hin,
                                                   const float* __restrict__ bias,
                                                   float* __restrict__ Hout) {
    int warp = (blockIdx.x * blockDim.x + threadIdx.x) >> 5;
    int lane = threadIdx.x & 31;
    if (warp >= NN) return;
    int beg = g_row_ptr[warp];
    int end = g_row_ptr[warp + 1];
    float4 a0 = make_float4(0.f, 0.f, 0.f, 0.f);
    float4 a1 = make_float4(0.f, 0.f, 0.f, 0.f);
    float4 a2 = make_float4(0.f, 0.f, 0.f, 0.f);
    float4 a3 = make_float4(0.f, 0.f, 0.f, 0.f);
    int e = beg;
    for (; e + 3 < end; e += 4) {   // 4-way MLP
        int s0 = g_csr_src[e],     s1 = g_csr_src[e + 1];
        int s2 = g_csr_src[e + 2], s3 = g_csr_src[e + 3];
        float4 v0 = __ldg((const float4*)(Hin + (size_t)s0 * HID) + lane);
        float4 v1 = __ldg((const float4*)(Hin + (size_t)s1 * HID) + lane);
        float4 v2 = __ldg((const float4*)(Hin + (size_t)s2 * HID) + lane);
        float4 v3 = __ldg((const float4*)(Hin + (size_t)s3 * HID) + lane);
        a0.x += v0.x; a0.y += v0.y; a0.z += v0.z; a0.w += v0.w;
        a1.x += v1.x; a1.y += v1.y; a1.z += v1.z; a1.w += v1.w;
        a2.x += v2.x; a2.y += v2.y; a2.z += v2.z; a2.w += v2.w;
        a3.x += v3.x; a3.y += v3.y; a3.z += v3.z; a3.w += v3.w;
    }
    for (; e < end; e++) {
        int s0 = g_csr_src[e];
        float4 v0 = __ldg((const float4*)(Hin + (size_t)s0 * HID) + lane);
        a0.x += v0.x; a0.y += v0.y; a0.z += v0.z; a0.w += v0.w;
    }
    a0.x += a1.x; a0.y += a1.y; a0.z += a1.z; a0.w += a1.w;
    a2.x += a3.x; a2.y += a3.y; a2.z += a3.z; a2.w += a3.w;
    a0.x += a2.x; a0.y += a2.y; a0.z += a2.z; a0.w += a2.w;
    float nd = g_norm_dst[warp];
    float4 b = __ldg((const float4*)bias + lane);
    float4 o;
    o.x = fmaxf(a0.x * nd + b.x, 0.f);
    o.y = fmaxf(a0.y * nd + b.y, 0.f);
    o.z = fmaxf(a0.z * nd + b.z, 0.f);
    o.w = fmaxf(a0.w * nd + b.w, 0.f);
    ((float4*)(Hout + (size_t)warp * HID))[lane] = o;
}

// ---------------- per-batch exact top-K via register-blocked bitonic sort ------
// key = (float_bits(v) << 32) | (NPER - i): relu => v >= 0 => bits monotone;
// descending sort; larger low field = smaller index wins ties (lax.top_k).
// Padding keys = 0 sort to the tail (real low field >= 1).
// Bank swizzle sw(i) = i ^ ((i>>4) & 15): bijective; maps the 16-consecutive-
// lane stride-16-element accesses onto 16 distinct banks (was 32-way conflict).
#define CHUNK 16
extern __shared__ unsigned long long s_key[];   // SORT_M * 8 = 128 KB dynamic

__device__ __forceinline__ int sw_idx(int i) { return i ^ ((i >> 4) & 15); }

__device__ __forceinline__ void local_ce(unsigned long long* v, int base, int k, int j) {
#pragma unroll
    for (int i = 0; i < CHUNK; i++) {
        int l = i ^ j;
        if (l > i) {
            bool desc = (((base + i) & k) == 0);
            unsigned long long a = v[i], c = v[l];
            if (desc ? (a < c) : (a > c)) { v[i] = c; v[l] = a; }
        }
    }
}

__global__ __launch_bounds__(1024) void k_sort(const float* __restrict__ H2) {
    int b = blockIdx.x;
    int t = threadIdx.x;
    int base = t * CHUNK;

    unsigned long long v[CHUNK];
#pragma unroll
    for (int q = 0; q < CHUNK; q++) {
        int i = base + q;
        unsigned long long key = 0ULL;
        if (i < NPER) {
            float val = H2[((size_t)(b * NPER + i)) * HID + 127] + 0.0f;  // -0 -> +0
            key = ((unsigned long long)__float_as_uint(val) << 32)
                  | (unsigned)(NPER - i);
        }
        v[q] = key;
    }
#pragma unroll
    for (int k = 2; k <= CHUNK; k <<= 1)
#pragma unroll
        for (int j = k >> 1; j >= 1; j >>= 1)
            local_ce(v, base, k, j);
#pragma unroll
    for (int q = 0; q < CHUNK; q++) s_key[sw_idx(base + q)] = v[q];
    __syncthreads();

    for (int k = 32; k <= SORT_M; k <<= 1) {
        for (int j = k >> 1; j >= CHUNK; j >>= 1) {
#pragma unroll
            for (int q = 0; q < CHUNK; q++) {
                int i = base + q;
                int l = i ^ j;
                if (l > i) {
                    int si = sw_idx(i), sl = sw_idx(l);
                    unsigned long long a = s_key[si];
                    unsigned long long c = s_key[sl];
                    bool desc = ((i & k) == 0);
                    if (desc ? (a < c) : (a > c)) { s_key[si] = c; s_key[sl] = a; }
                }
            }
            __syncthreads();
        }
#pragma unroll
        for (int q = 0; q < CHUNK; q++) v[q] = s_key[sw_idx(base + q)];
#pragma unroll
        for (int j = CHUNK >> 1; j >= 1; j >>= 1)
            local_ce(v, base, k, j);
#pragma unroll
        for (int q = 0; q < CHUNK; q++) s_key[sw_idx(base + q)] = v[q];
        __syncthreads();
    }

    for (int r = t; r < KSEL; r += 1024) {
        unsigned long long key = s_key[sw_idx(r)];
        int i = NPER - (int)(key & 0xffffffffu);
        g_sel[b * KSEL + r] = b * NPER + i;
    }
}

// ---------------- output: smem-staged pooled @ W3, W3 reused across batches ----
#define FIN_SMEM ((RPB * HID * NCLS + BATCH * RPB * HID) * (int)sizeof(float))  // 106496 B

extern __shared__ float s_fin[];   // [RPB*HID*NCLS] W slice, then [BATCH*RPB*HID] rows

__global__ __launch_bounds__(256) void k_final(const float* __restrict__ H2,
                                               const float* __restrict__ W3) {
    int t  = threadIdx.x;
    int r0 = blockIdx.x * RPB;

    float* sW = s_fin;                        // RPB*HID*NCLS floats
    float* sX = s_fin + RPB * HID * NCLS;     // BATCH*RPB*HID floats

    const float4* wsrc = (const float4*)(W3 + (size_t)r0 * HID * NCLS);
    const int WV = RPB * HID * NCLS / 4;      // 4608 float4
    for (int m = t; m < WV; m += 256)
        ((float4*)sW)[m] = __ldg(wsrc + m);

    {
        int warp = t >> 5, lane = t & 31;
        for (int p = warp; p < BATCH * RPB; p += 8) {
            int b = p >> 3, q = p & 7;
            int node = g_sel[b * KSEL + r0 + q];
            ((float4*)sX)[p * (HID / 4) + lane] =
                __ldg((const float4*)(H2 + (size_t)node * HID) + lane);
        }
    }
    __syncthreads();

    __shared__ float red[RPB * NCLS];
    for (int b = 0; b < BATCH; b++) {
        if (t < RPB * NCLS) {
            int q = t / NCLS, c = t % NCLS;
            const float* x = sX + (b * RPB + q) * HID;
            const float* w = sW + q * HID * NCLS + c;
            float acc = 0.f;
#pragma unroll 8
            for (int h = 0; h < HID; h++)
                acc += x[h] * w[h * NCLS];
            red[t] = acc;
        }
        __syncthreads();
        if (t < NCLS) {
            float s = 0.f;
#pragma unroll
            for (int q = 0; q < RPB; q++) s += red[q * NCLS + t];
            g_partial[((size_t)b * FIN_BLK + blockIdx.x) * NCLS + t] = s;
        }
        __syncthreads();
    }
}

// warp-per-output reduction: 18 blocks x 256 threads = 144 warps = BATCH*NCLS
__global__ __launch_bounds__(256) void k_reduce(const float* __restrict__ b3,
                                                float* __restrict__ out) {
    int w    = blockIdx.x * 8 + (threadIdx.x >> 5);   // output index 0..143
    int lane = threadIdx.x & 31;
    if (w >= BATCH * NCLS) return;
    int b = w / NCLS, c = w % NCLS;
    float s = 0.f;
    for (int blk = lane; blk < FIN_BLK; blk += 32)    // fixed per-lane order
        s += g_partial[((size_t)b * FIN_BLK + blk) * NCLS + c];
#pragma unroll
    for (int off = 16; off > 0; off >>= 1)            // fixed-tree reduce
        s += __shfl_down_sync(0xffffffffu, s, off);
    if (lane == 0) out[w] = s + __ldg(&b3[c]);
}

// ---------------- launch ----------------
extern "C" void kernel_launch(void* const* d_in, const int* in_sizes, int n_in,
                              void* d_out, int out_size) {
    const float* features = (const float*)d_in[0];
    const int*   src      = (const int*)  d_in[1];
    const int*   dst      = (const int*)  d_in[2];
    const float* W1       = (const float*)d_in[3];
    const float* b1       = (const float*)d_in[4];
    const float* W2       = (const float*)d_in[5];
    const float* b2       = (const float*)d_in[6];
    const float* W3       = (const float*)d_in[7];
    const float* b3       = (const float*)d_in[8];
    float* out = (float*)d_out;

    float *bufA, *bufB;
    cudaGetSymbolAddress((void**)&bufA, g_bufA);
    cudaGetSymbolAddress((void**)&bufB, g_bufB);

    cudaFuncSetAttribute(k_sort, cudaFuncAttributeMaxDynamicSharedMemorySize,
                         SORT_M * (int)sizeof(unsigned long long));
    cudaFuncSetAttribute(k_final, cudaFuncAttributeMaxDynamicSharedMemorySize,
                         FIN_SMEM);

    // 1) degrees + norms
    k_zero_deg<<<(NN + 255) / 256, 256>>>();
    k_degrees<<<(EE + 255) / 256, 256>>>(src, dst);
    k_norms<<<(NN + 255) / 256, 256>>>();

    // 2) CSR by dst (parallel 3-pass scan, then scatter)
    k_scan_a<<<SCAN_G, SCAN_B>>>();
    k_scan_b<<<1, 512>>>();
    k_scan_c<<<SCAN_G, SCAN_B>>>();
    k_csr_scatter<<<(EE + 255) / 256, 256>>>(src, dst);

    // 3) layer 1 (aggregate in 64-dim with fused src-norm, then transform)
    k_agg64<<<(NN * 32 + 255) / 256, 256>>>(features, bufB);
    k_gemm<IN_DIM, 1><<<(NN + 63) / 64, 256>>>(bufB, W1, b1, bufA);  // bufA = h1

    // 4) layer 2: transform+ns, gather-aggregate + relu(acc*nd + b2)
    k_gemm<HID, 0><<<(NN + 63) / 64, 256>>>(bufA, W2, nullptr, bufB);
    k_aggregate<<<(NN * 32 + 255) / 256, 256>>>(bufB, b2, bufA);     // bufA = h2

    // 5) exact per-batch top-K (register-blocked bitonic sort, 1 block/batch)
    k_sort<<<BATCH, 1024, SORT_M * sizeof(unsigned long long)>>>(bufA);

    // 6) pooled @ W3 + b3 (W3 slice shared across all batches; deterministic)
    k_final<<<FIN_BLK, 256, FIN_SMEM>>>(bufA, W3);
    k_reduce<<<18, 256>>>(b3, out);
}

// round 14
// speedup vs baseline: 2.3053x; 1.0227x over previous
#include <cuda_runtime.h>
#include <cuda_bf16.h>
#include <cstdint>

// Problem constants
#define NN      100000
#define EE      1600000
#define IN_DIM  64
#define HID     128
#define NCLS    18
#define BATCH   8
#define KSEL    5000
#define NPER    (NN / BATCH)   // 12500
#define SORT_M  16384          // next pow2 >= NPER
#define RPB     8              // ranks per block in k_final
#define FIN_BLK (KSEL / RPB)   // 625 rank-chunks
#define SCAN_B  256
#define SCAN_G  ((NN + SCAN_B - 1) / SCAN_B)   // 391

// ---------------- scratch (static device globals; no allocation) ----------------
__device__ float g_bufA[(size_t)NN * HID];   // 51.2 MB
__device__ float g_bufB[(size_t)NN * HID];   // 51.2 MB
__device__ int   g_out_deg[NN];
__device__ int   g_in_deg[NN];
__device__ float g_norm_src[NN];
__device__ float g_norm_dst[NN];
__device__ int   g_row_ptr[NN + 1];
__device__ int   g_pos[NN];
__device__ int   g_csr_src[EE];
__device__ int   g_blk[SCAN_G];
__device__ int   g_sel[BATCH * KSEL];                    // sel[b*K + rank] = global node id
__device__ float g_partial[BATCH * FIN_BLK * NCLS];      // deterministic reduction staging

// ---------------- degree ----------------
__global__ void k_zero_deg() {
    int i = blockIdx.x * blockDim.x + threadIdx.x;
    if (i < NN) { g_out_deg[i] = 0; g_in_deg[i] = 0; }
}

__global__ void k_degrees(const int* __restrict__ src, const int* __restrict__ dst) {
    int e2 = blockIdx.x * blockDim.x + threadIdx.x;   // 2 edges per thread
    if (e2 < EE / 2) {
        int2 s = __ldg((const int2*)src + e2);
        int2 d = __ldg((const int2*)dst + e2);
        atomicAdd(&g_out_deg[s.x], 1);
        atomicAdd(&g_out_deg[s.y], 1);
        atomicAdd(&g_in_deg[d.x], 1);
        atomicAdd(&g_in_deg[d.y], 1);
    }
}

// ---------------- CSR build: parallel 3-pass exclusive scan of in_deg ----------
__global__ __launch_bounds__(SCAN_B) void k_scan_a() {
    __shared__ int sh[SCAN_B];
    int t = threadIdx.x;
    int i = blockIdx.x * SCAN_B + t;
    sh[t] = (i < NN) ? g_in_deg[i] : 0;
    __syncthreads();
    for (int s = SCAN_B / 2; s > 0; s >>= 1) {
        if (t < s) sh[t] += sh[t + s];
        __syncthreads();
    }
    if (t == 0) g_blk[blockIdx.x] = sh[0];
}

__global__ __launch_bounds__(512) void k_scan_b() {
    __shared__ int sm[512];
    int t = threadIdx.x;
    sm[t] = (t < SCAN_G) ? g_blk[t] : 0;
    __syncthreads();
    for (int off = 1; off < 512; off <<= 1) {
        int v = (t >= off) ? sm[t - off] : 0;
        __syncthreads();
        sm[t] += v;
        __syncthreads();
    }
    if (t < SCAN_G) g_blk[t] = (t == 0) ? 0 : sm[t - 1];
    if (t == SCAN_G - 1) g_row_ptr[NN] = sm[t];   // == EE
}

// pass C: per-block scan + offsets; FUSED: also computes both norms
__global__ __launch_bounds__(SCAN_B) void k_scan_c() {
    __shared__ int sm[SCAN_B];
    int t = threadIdx.x;
    int i = blockIdx.x * SCAN_B + t;
    int v = (i < NN) ? g_in_deg[i] : 0;
    sm[t] = v;
    __syncthreads();
    for (int off = 1; off < SCAN_B; off <<= 1) {
        int u = (t >= off) ? sm[t - off] : 0;
        __syncthreads();
        sm[t] += u;
        __syncthreads();
    }
    if (i < NN) {
        int excl = g_blk[blockIdx.x] + sm[t] - v;
        g_row_ptr[i] = excl;
        g_pos[i]     = excl;
        int od = g_out_deg[i]; if (od < 1) od = 1;
        int id = v;            if (id < 1) id = 1;
        g_norm_src[i] = rsqrtf((float)od);
        g_norm_dst[i] = rsqrtf((float)id);
    }
}

__global__ void k_csr_scatter(const int* __restrict__ src, const int* __restrict__ dst) {
    int e = blockIdx.x * blockDim.x + threadIdx.x;
    if (e < EE) {
        int p = atomicAdd(&g_pos[dst[e]], 1);
        g_csr_src[p] = src[e];
    }
}

// ---------------- 64-dim CSR gather aggregation with fused src-norm ----------
// Hout[v,:] = sum_{e: dst==v} X[csr_src[e],:] * norm_src[csr_src[e]]
__global__ __launch_bounds__(256) void k_agg64(const float* __restrict__ X,
                                               float* __restrict__ Hout) {
    int warp = (blockIdx.x * blockDim.x + threadIdx.x) >> 5;
    int lane = threadIdx.x & 31;
    if (warp >= NN) return;
    int beg = g_row_ptr[warp];
    int end = g_row_ptr[warp + 1];
    float2 a0 = make_float2(0.f, 0.f), a1 = make_float2(0.f, 0.f);
    float2 a2 = make_float2(0.f, 0.f), a3 = make_float2(0.f, 0.f);
    int e = beg;
    for (; e + 3 < end; e += 4) {   // 4-way MLP
        int s0 = g_csr_src[e],     s1 = g_csr_src[e + 1];
        int s2 = g_csr_src[e + 2], s3 = g_csr_src[e + 3];
        float n0 = __ldg(&g_norm_src[s0]), n1 = __ldg(&g_norm_src[s1]);
        float n2 = __ldg(&g_norm_src[s2]), n3 = __ldg(&g_norm_src[s3]);
        float2 v0 = __ldg((const float2*)(X + (size_t)s0 * IN_DIM) + lane);
        float2 v1 = __ldg((const float2*)(X + (size_t)s1 * IN_DIM) + lane);
        float2 v2 = __ldg((const float2*)(X + (size_t)s2 * IN_DIM) + lane);
        float2 v3 = __ldg((const float2*)(X + (size_t)s3 * IN_DIM) + lane);
        a0.x += v0.x * n0; a0.y += v0.y * n0;
        a1.x += v1.x * n1; a1.y += v1.y * n1;
        a2.x += v2.x * n2; a2.y += v2.y * n2;
        a3.x += v3.x * n3; a3.y += v3.y * n3;
    }
    for (; e < end; e++) {
        int s0 = g_csr_src[e];
        float n0 = __ldg(&g_norm_src[s0]);
        float2 v0 = __ldg((const float2*)(X + (size_t)s0 * IN_DIM) + lane);
        a0.x += v0.x * n0; a0.y += v0.y * n0;
    }
    a0.x += a1.x; a0.y += a1.y;
    a2.x += a3.x; a2.y += a3.y;
    a0.x += a2.x; a0.y += a2.y;
    ((float2*)(Hout + (size_t)warp * IN_DIM))[lane] = a0;
}

// ---------------- dense transform ----------------
// POST=1: Out[i,:] = relu((A[i,:KD] @ W) * norm_dst[i] + bias)   (layer-1 tail)
// POST=0: Out[i,:] = (A[i,:KD] @ W) * norm_src[i]                (layer-2 head)
template <int KD, int POST>
__global__ __launch_bounds__(256) void k_gemm(const float* __restrict__ A,
                                              const float* __restrict__ W,
                                              const float* __restrict__ bias,
                                              float* __restrict__ Out) {
    const int TM = 64;
    __shared__ float As[TM][32];      // 8 KB
    __shared__ float Bs[32][HID];     // 16 KB
    int t  = threadIdx.x;
    int tx = t & 31;                  // col group: cols tx*4 .. tx*4+3
    int ty = t >> 5;                  // row group: rows ty*8 .. ty*8+7
    int row0 = blockIdx.x * TM;

    float acc[8][4];
#pragma unroll
    for (int r = 0; r < 8; r++)
#pragma unroll
        for (int c = 0; c < 4; c++) acc[r][c] = 0.f;

    for (int kk = 0; kk < KD; kk += 32) {
#pragma unroll
        for (int j = 0; j < 8; j++) {      // 2048 elems of As
            int m = t + j * 256;
            int r = m >> 5, c = m & 31;
            int gr = row0 + r;
            As[r][c] = (gr < NN) ? A[(size_t)gr * KD + kk + c] : 0.f;
        }
#pragma unroll
        for (int j = 0; j < 16; j++) {     // 4096 elems of Bs
            int m = t + j * 256;
            int r = m >> 7, c = m & 127;
            Bs[r][c] = W[(size_t)(kk + r) * HID + c];
        }
        __syncthreads();
#pragma unroll
        for (int k4 = 0; k4 < 8; k4++) {   // 4 K-steps per iter, float4 As reads
            float4 b0 = *(const float4*)&Bs[k4 * 4 + 0][tx * 4];
            float4 b1 = *(const float4*)&Bs[k4 * 4 + 1][tx * 4];
            float4 b2 = *(const float4*)&Bs[k4 * 4 + 2][tx * 4];
            float4 b3 = *(const float4*)&Bs[k4 * 4 + 3][tx * 4];
#pragma unroll
            for (int r = 0; r < 8; r++) {
                float4 a = *(const float4*)&As[ty * 8 + r][k4 * 4];
                acc[r][0] += a.x * b0.x + a.y * b1.x + a.z * b2.x + a.w * b3.x;
                acc[r][1] += a.x * b0.y + a.y * b1.y + a.z * b2.y + a.w * b3.y;
                acc[r][2] += a.x * b0.z + a.y * b1.z + a.z * b2.z + a.w * b3.z;
                acc[r][3] += a.x * b0.w + a.y * b1.w + a.z * b2.w + a.w * b3.w;
            }
        }
        __syncthreads();
    }
#pragma unroll
    for (int r = 0; r < 8; r++) {
        int gr = row0 + ty * 8 + r;
        if (gr < NN) {
            float4 o;
            if (POST) {
                float nd = g_norm_dst[gr];
                float4 b = __ldg((const float4*)bias + tx);
                o.x = fmaxf(acc[r][0] * nd + b.x, 0.f);
                o.y = fmaxf(acc[r][1] * nd + b.y, 0.f);
                o.z = fmaxf(acc[r][2] * nd + b.z, 0.f);
                o.w = fmaxf(acc[r][3] * nd + b.w, 0.f);
            } else {
                float ns = g_norm_src[gr];
                o.x = acc[r][0] * ns; o.y = acc[r][1] * ns;
                o.z = acc[r][2] * ns; o.w = acc[r][3] * ns;
            }
            *(float4*)&Out[(size_t)gr * HID + tx * 4] = o;
        }
    }
}

// ---------------- 128-dim CSR gather aggregation + bias + relu ----------------
__global__ __launch_bounds__(256) void k_aggregate(const float* __restrict__ Hin,
                                                   const float* __restrict__ bias,
                                                   float* __restrict__ Hout) {
    int warp = (blockIdx.x * blockDim.x + threadIdx.x) >> 5;
    int lane = threadIdx.x & 31;
    if (warp >= NN) return;
    int beg = g_row_ptr[warp];
    int end = g_row_ptr[warp + 1];
    float4 a0 = make_float4(0.f, 0.f, 0.f, 0.f);
    float4 a1 = make_float4(0.f, 0.f, 0.f, 0.f);
    float4 a2 = make_float4(0.f, 0.f, 0.f, 0.f);
    float4 a3 = make_float4(0.f, 0.f, 0.f, 0.f);
    int e = beg;
    for (; e + 3 < end; e += 4) {   // 4-way MLP
        int s0 = g_csr_src[e],     s1 = g_csr_src[e + 1];
        int s2 = g_csr_src[e + 2], s3 = g_csr_src[e + 3];
        float4 v0 = __ldg((const float4*)(Hin + (size_t)s0 * HID) + lane);
        float4 v1 = __ldg((const float4*)(Hin + (size_t)s1 * HID) + lane);
        float4 v2 = __ldg((const float4*)(Hin + (size_t)s2 * HID) + lane);
        float4 v3 = __ldg((const float4*)(Hin + (size_t)s3 * HID) + lane);
        a0.x += v0.x; a0.y += v0.y; a0.z += v0.z; a0.w += v0.w;
        a1.x += v1.x; a1.y += v1.y; a1.z += v1.z; a1.w += v1.w;
        a2.x += v2.x; a2.y += v2.y; a2.z += v2.z; a2.w += v2.w;
        a3.x += v3.x; a3.y += v3.y; a3.z += v3.z; a3.w += v3.w;
    }
    for (; e < end; e++) {
        int s0 = g_csr_src[e];
        float4 v0 = __ldg((const float4*)(Hin + (size_t)s0 * HID) + lane);
        a0.x += v0.x; a0.y += v0.y; a0.z += v0.z; a0.w += v0.w;
    }
    a0.x += a1.x; a0.y += a1.y; a0.z += a1.z; a0.w += a1.w;
    a2.x += a3.x; a2.y += a3.y; a2.z += a3.z; a2.w += a3.w;
    a0.x += a2.x; a0.y += a2.y; a0.z += a2.z; a0.w += a2.w;
    float nd = g_norm_dst[warp];
    float4 b = __ldg((const float4*)bias + lane);
    float4 o;
    o.x = fmaxf(a0.x * nd + b.x, 0.f);
    o.y = fmaxf(a0.y * nd + b.y, 0.f);
    o.z = fmaxf(a0.z * nd + b.z, 0.f);
    o.w = fmaxf(a0.w * nd + b.w, 0.f);
    ((float4*)(Hout + (size_t)warp * HID))[lane] = o;
}

// ---------------- per-batch exact top-K via register-blocked bitonic sort ------
// key = (float_bits(v) << 32) | (NPER - i): relu => v >= 0 => bits monotone;
// descending sort; larger low field = smaller index wins ties (lax.top_k).
// Padding keys = 0 sort to the tail (real low field >= 1).
// Bank swizzle sw(i) = i ^ ((i>>4) & 15): bijective; maps the 16-consecutive-
// lane stride-16-element accesses onto 16 distinct banks (was 32-way conflict).
#define CHUNK 16
extern __shared__ unsigned long long s_key[];   // SORT_M * 8 = 128 KB dynamic

__device__ __forceinline__ int sw_idx(int i) { return i ^ ((i >> 4) & 15); }

__device__ __forceinline__ void local_ce(unsigned long long* v, int base, int k, int j) {
#pragma unroll
    for (int i = 0; i < CHUNK; i++) {
        int l = i ^ j;
        if (l > i) {
            bool desc = (((base + i) & k) == 0);
            unsigned long long a = v[i], c = v[l];
            if (desc ? (a < c) : (a > c)) { v[i] = c; v[l] = a; }
        }
    }
}

__global__ __launch_bounds__(1024) void k_sort(const float* __restrict__ H2) {
    int b = blockIdx.x;
    int t = threadIdx.x;
    int base = t * CHUNK;

    unsigned long long v[CHUNK];
#pragma unroll
    for (int q = 0; q < CHUNK; q++) {
        int i = base + q;
        unsigned long long key = 0ULL;
        if (i < NPER) {
            float val = H2[((size_t)(b * NPER + i)) * HID + 127] + 0.0f;  // -0 -> +0
            key = ((unsigned long long)__float_as_uint(val) << 32)
                  | (unsigned)(NPER - i);
        }
        v[q] = key;
    }
#pragma unroll
    for (int k = 2; k <= CHUNK; k <<= 1)
#pragma unroll
        for (int j = k >> 1; j >= 1; j >>= 1)
            local_ce(v, base, k, j);
#pragma unroll
    for (int q = 0; q < CHUNK; q++) s_key[sw_idx(base + q)] = v[q];
    __syncthreads();

    for (int k = 32; k <= SORT_M; k <<= 1) {
        for (int j = k >> 1; j >= CHUNK; j >>= 1) {
#pragma unroll
            for (int q = 0; q < CHUNK; q++) {
                int i = base + q;
                int l = i ^ j;
                if (l > i) {
                    int si = sw_idx(i), sl = sw_idx(l);
                    unsigned long long a = s_key[si];
                    unsigned long long c = s_key[sl];
                    bool desc = ((i & k) == 0);
                    if (desc ? (a < c) : (a > c)) { s_key[si] = c; s_key[sl] = a; }
                }
            }
            __syncthreads();
        }
#pragma unroll
        for (int q = 0; q < CHUNK; q++) v[q] = s_key[sw_idx(base + q)];
#pragma unroll
        for (int j = CHUNK >> 1; j >= 1; j >>= 1)
            local_ce(v, base, k, j);
#pragma unroll
        for (int q = 0; q < CHUNK; q++) s_key[sw_idx(base + q)] = v[q];
        __syncthreads();
    }

    for (int r = t; r < KSEL; r += 1024) {
        unsigned long long key = s_key[sw_idx(r)];
        int i = NPER - (int)(key & 0xffffffffu);
        g_sel[b * KSEL + r] = b * NPER + i;
    }
}

// ---------------- output: smem-staged pooled @ W3, W3 reused across batches ----
// W3 slice staged TRANSPOSED: sWT[q][c][h], row stride WT_STR floats.
// WT_STR = 132: 132*4B = 528B = 33*16B (float4-aligned rows), 132 mod 32 = 4
// (c, c+8 share a bank -> ~2-way, vs 18-way unpadded). Inner loop is float4
// on both operands.
#define WT_STR   132
#define WT_Q     (NCLS * WT_STR)                       // 2376 floats per rank
#define FIN_SMEM ((RPB * WT_Q + BATCH * RPB * HID) * (int)sizeof(float))  // 108800 B

extern __shared__ float s_fin[];   // [RPB*WT_Q] W transposed, then [BATCH*RPB*HID] rows

__global__ __launch_bounds__(256) void k_final(const float* __restrict__ H2,
                                               const float* __restrict__ W3) {
    int t  = threadIdx.x;
    int r0 = blockIdx.x * RPB;

    float* sWT = s_fin;                       // RPB*WT_Q floats
    float* sX  = s_fin + RPB * WT_Q;          // BATCH*RPB*HID floats

    // stage W3 slice transposed: float4 gmem reads, scalar smem writes
    const float4* wsrc = (const float4*)(W3 + (size_t)r0 * HID * NCLS);
    const int WV = RPB * HID * NCLS / 4;      // 4608 float4
    for (int m4 = t; m4 < WV; m4 += 256) {
        float4 w = __ldg(wsrc + m4);
        int m = m4 * 4;
#pragma unroll
        for (int j = 0; j < 4; j++) {
            int mm = m + j;
            int q  = mm / (HID * NCLS);
            int r  = mm % (HID * NCLS);
            int h  = r / NCLS;
            int c  = r % NCLS;
            float val = (j == 0) ? w.x : (j == 1) ? w.y : (j == 2) ? w.z : w.w;
            sWT[q * WT_Q + c * WT_STR + h] = val;
        }
    }

    // stage 64 H2 rows (8 batches x 8 ranks); one warp per row per iteration
    {
        int warp = t >> 5, lane = t & 31;
        for (int p = warp; p < BATCH * RPB; p += 8) {
            int b = p >> 3, q = p & 7;
            int node = g_sel[b * KSEL + r0 + q];
            ((float4*)sX)[p * (HID / 4) + lane] =
                __ldg((const float4*)(H2 + (size_t)node * HID) + lane);
        }
    }
    __syncthreads();

    __shared__ float red[RPB * NCLS];
    for (int b = 0; b < BATCH; b++) {
        if (t < RPB * NCLS) {
            int q = t / NCLS, c = t % NCLS;
            const float4* x = (const float4*)(sX + (b * RPB + q) * HID);
            const float4* w = (const float4*)(sWT + q * WT_Q + c * WT_STR);
            float acc = 0.f;
#pragma unroll 8
            for (int h4 = 0; h4 < HID / 4; h4++) {
                float4 xv = x[h4];
                float4 wv = w[h4];
                acc += xv.x * wv.x + xv.y * wv.y + xv.z * wv.z + xv.w * wv.w;
            }
            red[t] = acc;
        }
        __syncthreads();
        if (t < NCLS) {
            float s = 0.f;
#pragma unroll
            for (int q = 0; q < RPB; q++) s += red[q * NCLS + t];
            g_partial[((size_t)b * FIN_BLK + blockIdx.x) * NCLS + t] = s;
        }
        __syncthreads();
    }
}

// warp-per-output reduction: 18 blocks x 256 threads = 144 warps = BATCH*NCLS
__global__ __launch_bounds__(256) void k_reduce(const float* __restrict__ b3,
                                                float* __restrict__ out) {
    int w    = blockIdx.x * 8 + (threadIdx.x >> 5);   // output index 0..143
    int lane = threadIdx.x & 31;
    if (w >= BATCH * NCLS) return;
    int b = w / NCLS, c = w % NCLS;
    float s = 0.f;
    for (int blk = lane; blk < FIN_BLK; blk += 32)    // fixed per-lane order
        s += g_partial[((size_t)b * FIN_BLK + blk) * NCLS + c];
#pragma unroll
    for (int off = 16; off > 0; off >>= 1)            // fixed-tree reduce
        s += __shfl_down_sync(0xffffffffu, s, off);
    if (lane == 0) out[w] = s + __ldg(&b3[c]);
}

// ---------------- launch ----------------
extern "C" void kernel_launch(void* const* d_in, const int* in_sizes, int n_in,
                              void* d_out, int out_size) {
    const float* features = (const float*)d_in[0];
    const int*   src      = (const int*)  d_in[1];
    const int*   dst      = (const int*)  d_in[2];
    const float* W1       = (const float*)d_in[3];
    const float* b1       = (const float*)d_in[4];
    const float* W2       = (const float*)d_in[5];
    const float* b2       = (const float*)d_in[6];
    const float* W3       = (const float*)d_in[7];
    const float* b3       = (const float*)d_in[8];
    float* out = (float*)d_out;

    float *bufA, *bufB;
    cudaGetSymbolAddress((void**)&bufA, g_bufA);
    cudaGetSymbolAddress((void**)&bufB, g_bufB);

    cudaFuncSetAttribute(k_sort, cudaFuncAttributeMaxDynamicSharedMemorySize,
                         SORT_M * (int)sizeof(unsigned long long));
    cudaFuncSetAttribute(k_final, cudaFuncAttributeMaxDynamicSharedMemorySize,
                         FIN_SMEM);

    // 1) degrees
    k_zero_deg<<<(NN + 255) / 256, 256>>>();
    k_degrees<<<(EE / 2 + 255) / 256, 256>>>(src, dst);

    // 2) CSR by dst (parallel 3-pass scan w/ fused norms, then scatter)
    k_scan_a<<<SCAN_G, SCAN_B>>>();
    k_scan_b<<<1, 512>>>();
    k_scan_c<<<SCAN_G, SCAN_B>>>();
    k_csr_scatter<<<(EE + 255) / 256, 256>>>(src, dst);

    // 3) layer 1 (aggregate in 64-dim with fused src-norm, then transform)
    k_agg64<<<(NN * 32 + 255) / 256, 256>>>(features, bufB);
    k_gemm<IN_DIM, 1><<<(NN + 63) / 64, 256>>>(bufB, W1, b1, bufA);  // bufA = h1

    // 4) layer 2: transform+ns, gather-aggregate + relu(acc*nd + b2)
    k_gemm<HID, 0><<<(NN + 63) / 64, 256>>>(bufA, W2, nullptr, bufB);
    k_aggregate<<<(NN * 32 + 255) / 256, 256>>>(bufB, b2, bufA);     // bufA = h2

    // 5) exact per-batch top-K (register-blocked bitonic sort, 1 block/batch)
    k_sort<<<BATCH, 1024, SORT_M * sizeof(unsigned long long)>>>(bufA);

    // 6) pooled @ W3 + b3 (transposed W slice shared across batches; deterministic)
    k_final<<<FIN_BLK, 256, FIN_SMEM>>>(bufA, W3);
    k_reduce<<<18, 256>>>(b3, out);
}

// round 15
// speedup vs baseline: 2.4354x; 1.0564x over previous
#include <cuda_runtime.h>
#include <cuda_bf16.h>
#include <cstdint>

// Problem constants
#define NN      100000
#define EE      1600000
#define IN_DIM  64
#define HID     128
#define NCLS    18
#define BATCH   8
#define KSEL    5000
#define NPER    (NN / BATCH)   // 12500
#define SORT_M  16384          // next pow2 >= NPER
#define RPB     8              // ranks per block in k_final
#define FIN_BLK (KSEL / RPB)   // 625 rank-chunks
#define SCAN_B  256
#define SCAN_G  ((NN + SCAN_B - 1) / SCAN_B)   // 391
#define NSEL    (BATCH * KSEL) // 40000 selected rows

// ---------------- scratch (static device globals; no allocation) ----------------
__device__ float g_bufA[(size_t)NN * HID];   // 51.2 MB  (h1, later H2 compact)
__device__ float g_bufB[(size_t)NN * HID];   // 51.2 MB  (agg64, later agg2)
__device__ int   g_out_deg[NN];
__device__ int   g_in_deg[NN];
__device__ float g_norm_src[NN];
__device__ float g_norm_dst[NN];
__device__ int   g_row_ptr[NN + 1];
__device__ int   g_pos[NN];
__device__ int   g_csr_src[EE];
__device__ int   g_blk[SCAN_G];
__device__ float g_keyf[NN];                             // sort key = H2[:,127]
__device__ int   g_sel[BATCH * KSEL];                    // sel[b*K + rank] = global node id
__device__ float g_partial[BATCH * FIN_BLK * NCLS];      // deterministic reduction staging

// ---------------- degree ----------------
__global__ void k_zero_deg() {
    int i = blockIdx.x * blockDim.x + threadIdx.x;
    if (i < NN) { g_out_deg[i] = 0; g_in_deg[i] = 0; }
}

__global__ void k_degrees(const int* __restrict__ src, const int* __restrict__ dst) {
    int e2 = blockIdx.x * blockDim.x + threadIdx.x;   // 2 edges per thread
    if (e2 < EE / 2) {
        int2 s = __ldg((const int2*)src + e2);
        int2 d = __ldg((const int2*)dst + e2);
        atomicAdd(&g_out_deg[s.x], 1);
        atomicAdd(&g_out_deg[s.y], 1);
        atomicAdd(&g_in_deg[d.x], 1);
        atomicAdd(&g_in_deg[d.y], 1);
    }
}

// ---------------- CSR build: parallel 3-pass exclusive scan of in_deg ----------
__global__ __launch_bounds__(SCAN_B) void k_scan_a() {
    __shared__ int sh[SCAN_B];
    int t = threadIdx.x;
    int i = blockIdx.x * SCAN_B + t;
    sh[t] = (i < NN) ? g_in_deg[i] : 0;
    __syncthreads();
    for (int s = SCAN_B / 2; s > 0; s >>= 1) {
        if (t < s) sh[t] += sh[t + s];
        __syncthreads();
    }
    if (t == 0) g_blk[blockIdx.x] = sh[0];
}

__global__ __launch_bounds__(512) void k_scan_b() {
    __shared__ int sm[512];
    int t = threadIdx.x;
    sm[t] = (t < SCAN_G) ? g_blk[t] : 0;
    __syncthreads();
    for (int off = 1; off < 512; off <<= 1) {
        int v = (t >= off) ? sm[t - off] : 0;
        __syncthreads();
        sm[t] += v;
        __syncthreads();
    }
    if (t < SCAN_G) g_blk[t] = (t == 0) ? 0 : sm[t - 1];
    if (t == SCAN_G - 1) g_row_ptr[NN] = sm[t];   // == EE
}

// pass C: per-block scan + offsets; FUSED: also computes both norms
__global__ __launch_bounds__(SCAN_B) void k_scan_c() {
    __shared__ int sm[SCAN_B];
    int t = threadIdx.x;
    int i = blockIdx.x * SCAN_B + t;
    int v = (i < NN) ? g_in_deg[i] : 0;
    sm[t] = v;
    __syncthreads();
    for (int off = 1; off < SCAN_B; off <<= 1) {
        int u = (t >= off) ? sm[t - off] : 0;
        __syncthreads();
        sm[t] += u;
        __syncthreads();
    }
    if (i < NN) {
        int excl = g_blk[blockIdx.x] + sm[t] - v;
        g_row_ptr[i] = excl;
        g_pos[i]     = excl;
        int od = g_out_deg[i]; if (od < 1) od = 1;
        int id = v;            if (id < 1) id = 1;
        g_norm_src[i] = rsqrtf((float)od);
        g_norm_dst[i] = rsqrtf((float)id);
    }
}

__global__ void k_csr_scatter(const int* __restrict__ src, const int* __restrict__ dst) {
    int e = blockIdx.x * blockDim.x + threadIdx.x;
    if (e < EE) {
        int p = atomicAdd(&g_pos[dst[e]], 1);
        g_csr_src[p] = src[e];
    }
}

// ---------------- 64-dim CSR gather aggregation with fused src-norm ----------
__global__ __launch_bounds__(256) void k_agg64(const float* __restrict__ X,
                                               float* __restrict__ Hout) {
    int warp = (blockIdx.x * blockDim.x + threadIdx.x) >> 5;
    int lane = threadIdx.x & 31;
    if (warp >= NN) return;
    int beg = g_row_ptr[warp];
    int end = g_row_ptr[warp + 1];
    float2 a0 = make_float2(0.f, 0.f), a1 = make_float2(0.f, 0.f);
    float2 a2 = make_float2(0.f, 0.f), a3 = make_float2(0.f, 0.f);
    int e = beg;
    for (; e + 3 < end; e += 4) {   // 4-way MLP
        int s0 = g_csr_src[e],     s1 = g_csr_src[e + 1];
        int s2 = g_csr_src[e + 2], s3 = g_csr_src[e + 3];
        float n0 = __ldg(&g_norm_src[s0]), n1 = __ldg(&g_norm_src[s1]);
        float n2 = __ldg(&g_norm_src[s2]), n3 = __ldg(&g_norm_src[s3]);
        float2 v0 = __ldg((const float2*)(X + (size_t)s0 * IN_DIM) + lane);
        float2 v1 = __ldg((const float2*)(X + (size_t)s1 * IN_DIM) + lane);
        float2 v2 = __ldg((const float2*)(X + (size_t)s2 * IN_DIM) + lane);
        float2 v3 = __ldg((const float2*)(X + (size_t)s3 * IN_DIM) + lane);
        a0.x += v0.x * n0; a0.y += v0.y * n0;
        a1.x += v1.x * n1; a1.y += v1.y * n1;
        a2.x += v2.x * n2; a2.y += v2.y * n2;
        a3.x += v3.x * n3; a3.y += v3.y * n3;
    }
    for (; e < end; e++) {
        int s0 = g_csr_src[e];
        float n0 = __ldg(&g_norm_src[s0]);
        float2 v0 = __ldg((const float2*)(X + (size_t)s0 * IN_DIM) + lane);
        a0.x += v0.x * n0; a0.y += v0.y * n0;
    }
    a0.x += a1.x; a0.y += a1.y;
    a2.x += a3.x; a2.y += a3.y;
    a0.x += a2.x; a0.y += a2.y;
    ((float2*)(Hout + (size_t)warp * IN_DIM))[lane] = a0;
}

// ---------------- 128-dim CSR gather aggregation with fused src-norm ----------
// agg2[v,:] = sum_{e: dst==v} Hin[csr_src[e],:] * norm_src[csr_src[e]]
__global__ __launch_bounds__(256) void k_agg128(const float* __restrict__ Hin,
                                                float* __restrict__ Hout) {
    int warp = (blockIdx.x * blockDim.x + threadIdx.x) >> 5;
    int lane = threadIdx.x & 31;
    if (warp >= NN) return;
    int beg = g_row_ptr[warp];
    int end = g_row_ptr[warp + 1];
    float4 a0 = make_float4(0.f, 0.f, 0.f, 0.f);
    float4 a1 = make_float4(0.f, 0.f, 0.f, 0.f);
    float4 a2 = make_float4(0.f, 0.f, 0.f, 0.f);
    float4 a3 = make_float4(0.f, 0.f, 0.f, 0.f);
    int e = beg;
    for (; e + 3 < end; e += 4) {   // 4-way MLP
        int s0 = g_csr_src[e],     s1 = g_csr_src[e + 1];
        int s2 = g_csr_src[e + 2], s3 = g_csr_src[e + 3];
        float n0 = __ldg(&g_norm_src[s0]), n1 = __ldg(&g_norm_src[s1]);
        float n2 = __ldg(&g_norm_src[s2]), n3 = __ldg(&g_norm_src[s3]);
        float4 v0 = __ldg((const float4*)(Hin + (size_t)s0 * HID) + lane);
        float4 v1 = __ldg((const float4*)(Hin + (size_t)s1 * HID) + lane);
        float4 v2 = __ldg((const float4*)(Hin + (size_t)s2 * HID) + lane);
        float4 v3 = __ldg((const float4*)(Hin + (size_t)s3 * HID) + lane);
        a0.x += v0.x * n0; a0.y += v0.y * n0; a0.z += v0.z * n0; a0.w += v0.w * n0;
        a1.x += v1.x * n1; a1.y += v1.y * n1; a1.z += v1.z * n1; a1.w += v1.w * n1;
        a2.x += v2.x * n2; a2.y += v2.y * n2; a2.z += v2.z * n2; a2.w += v2.w * n2;
        a3.x += v3.x * n3; a3.y += v3.y * n3; a3.z += v3.z * n3; a3.w += v3.w * n3;
    }
    for (; e < end; e++) {
        int s0 = g_csr_src[e];
        float n0 = __ldg(&g_norm_src[s0]);
        float4 v0 = __ldg((const float4*)(Hin + (size_t)s0 * HID) + lane);
        a0.x += v0.x * n0; a0.y += v0.y * n0; a0.z += v0.z * n0; a0.w += v0.w * n0;
    }
    a0.x += a1.x; a0.y += a1.y; a0.z += a1.z; a0.w += a1.w;
    a2.x += a3.x; a2.y += a3.y; a2.z += a3.z; a2.w += a3.w;
    a0.x += a2.x; a0.y += a2.y; a0.z += a2.z; a0.w += a2.w;
    ((float4*)(Hout + (size_t)warp * HID))[lane] = a0;
}

// ---------------- layer-1 dense transform (unchanged core) ----------------
// Out[i,:] = relu((A[i,:IN_DIM] @ W) * norm_dst[i] + bias)
__global__ __launch_bounds__(256) void k_gemm1(const float* __restrict__ A,
                                               const float* __restrict__ W,
                                               const float* __restrict__ bias,
                                               float* __restrict__ Out) {
    const int TM = 64;
    const int KD = IN_DIM;
    __shared__ float As[TM][32];
    __shared__ float Bs[32][HID];
    int t  = threadIdx.x;
    int tx = t & 31;
    int ty = t >> 5;
    int row0 = blockIdx.x * TM;

    float acc[8][4];
#pragma unroll
    for (int r = 0; r < 8; r++)
#pragma unroll
        for (int c = 0; c < 4; c++) acc[r][c] = 0.f;

    for (int kk = 0; kk < KD; kk += 32) {
#pragma unroll
        for (int j = 0; j < 8; j++) {
            int m = t + j * 256;
            int r = m >> 5, c = m & 31;
            int gr = row0 + r;
            As[r][c] = (gr < NN) ? A[(size_t)gr * KD + kk + c] : 0.f;
        }
#pragma unroll
        for (int j = 0; j < 16; j++) {
            int m = t + j * 256;
            int r = m >> 7, c = m & 127;
            Bs[r][c] = W[(size_t)(kk + r) * HID + c];
        }
        __syncthreads();
#pragma unroll
        for (int k4 = 0; k4 < 8; k4++) {
            float4 b0 = *(const float4*)&Bs[k4 * 4 + 0][tx * 4];
            float4 b1 = *(const float4*)&Bs[k4 * 4 + 1][tx * 4];
            float4 b2 = *(const float4*)&Bs[k4 * 4 + 2][tx * 4];
            float4 b3 = *(const float4*)&Bs[k4 * 4 + 3][tx * 4];
#pragma unroll
            for (int r = 0; r < 8; r++) {
                float4 a = *(const float4*)&As[ty * 8 + r][k4 * 4];
                acc[r][0] += a.x * b0.x + a.y * b1.x + a.z * b2.x + a.w * b3.x;
                acc[r][1] += a.x * b0.y + a.y * b1.y + a.z * b2.y + a.w * b3.y;
                acc[r][2] += a.x * b0.z + a.y * b1.z + a.z * b2.z + a.w * b3.z;
                acc[r][3] += a.x * b0.w + a.y * b1.w + a.z * b2.w + a.w * b3.w;
            }
        }
        __syncthreads();
    }
#pragma unroll
    for (int r = 0; r < 8; r++) {
        int gr = row0 + ty * 8 + r;
        if (gr < NN) {
            float nd = g_norm_dst[gr];
            float4 b = __ldg((const float4*)bias + tx);
            float4 o;
            o.x = fmaxf(acc[r][0] * nd + b.x, 0.f);
            o.y = fmaxf(acc[r][1] * nd + b.y, 0.f);
            o.z = fmaxf(acc[r][2] * nd + b.z, 0.f);
            o.w = fmaxf(acc[r][3] * nd + b.w, 0.f);
            *(float4*)&Out[(size_t)gr * HID + tx * 4] = o;
        }
    }
}

// ---------------- column-127 GEMV: sort keys for all nodes ----------------
// key[i] = relu(dot(agg2[i,:], W2[:,127]) * norm_dst[i] + b2[127])
__global__ __launch_bounds__(256) void k_colgemm(const float* __restrict__ A,
                                                 const float* __restrict__ W2,
                                                 const float* __restrict__ b2) {
    __shared__ float wcol[HID];
    int t = threadIdx.x;
    if (t < HID) wcol[t] = __ldg(&W2[(size_t)t * HID + 127]);
    __syncthreads();
    int warp = (blockIdx.x * blockDim.x + t) >> 5;
    int lane = t & 31;
    if (warp >= NN) return;
    float4 av = __ldg((const float4*)(A + (size_t)warp * HID) + lane);
    float4 wv = *(const float4*)&wcol[lane * 4];
    float d = av.x * wv.x + av.y * wv.y + av.z * wv.z + av.w * wv.w;
#pragma unroll
    for (int off = 16; off > 0; off >>= 1)
        d += __shfl_down_sync(0xffffffffu, d, off);
    if (lane == 0)
        g_keyf[warp] = fmaxf(d * g_norm_dst[warp] + __ldg(&b2[127]), 0.f);
}

// ---------------- per-batch exact top-K via register-blocked bitonic sort ------
// key = (float_bits(v) << 32) | (NPER - i): relu => v >= 0 => bits monotone;
// descending sort; larger low field = smaller index wins ties (lax.top_k).
// Padding keys = 0 sort to the tail (real low field >= 1).
// Bank swizzle sw(i) = i ^ ((i>>4) & 15): conflict-free smem passes.
#define CHUNK 16
extern __shared__ unsigned long long s_key[];   // SORT_M * 8 = 128 KB dynamic

__device__ __forceinline__ int sw_idx(int i) { return i ^ ((i >> 4) & 15); }

__device__ __forceinline__ void local_ce(unsigned long long* v, int base, int k, int j) {
#pragma unroll
    for (int i = 0; i < CHUNK; i++) {
        int l = i ^ j;
        if (l > i) {
            bool desc = (((base + i) & k) == 0);
            unsigned long long a = v[i], c = v[l];
            if (desc ? (a < c) : (a > c)) { v[i] = c; v[l] = a; }
        }
    }
}

__global__ __launch_bounds__(1024) void k_sort() {
    int b = blockIdx.x;
    int t = threadIdx.x;
    int base = t * CHUNK;

    unsigned long long v[CHUNK];
#pragma unroll
    for (int q = 0; q < CHUNK; q++) {
        int i = base + q;
        unsigned long long key = 0ULL;
        if (i < NPER) {
            float val = g_keyf[b * NPER + i] + 0.0f;   // -0 -> +0
            key = ((unsigned long long)__float_as_uint(val) << 32)
                  | (unsigned)(NPER - i);
        }
        v[q] = key;
    }
#pragma unroll
    for (int k = 2; k <= CHUNK; k <<= 1)
#pragma unroll
        for (int j = k >> 1; j >= 1; j >>= 1)
            local_ce(v, base, k, j);
#pragma unroll
    for (int q = 0; q < CHUNK; q++) s_key[sw_idx(base + q)] = v[q];
    __syncthreads();

    for (int k = 32; k <= SORT_M; k <<= 1) {
        for (int j = k >> 1; j >= CHUNK; j >>= 1) {
#pragma unroll
            for (int q = 0; q < CHUNK; q++) {
                int i = base + q;
                int l = i ^ j;
                if (l > i) {
                    int si = sw_idx(i), sl = sw_idx(l);
                    unsigned long long a = s_key[si];
                    unsigned long long c = s_key[sl];
                    bool desc = ((i & k) == 0);
                    if (desc ? (a < c) : (a > c)) { s_key[si] = c; s_key[sl] = a; }
                }
            }
            __syncthreads();
        }
#pragma unroll
        for (int q = 0; q < CHUNK; q++) v[q] = s_key[sw_idx(base + q)];
#pragma unroll
        for (int j = CHUNK >> 1; j >= 1; j >>= 1)
            local_ce(v, base, k, j);
#pragma unroll
        for (int q = 0; q < CHUNK; q++) s_key[sw_idx(base + q)] = v[q];
        __syncthreads();
    }

    for (int r = t; r < KSEL; r += 1024) {
        unsigned long long key = s_key[sw_idx(r)];
        int i = NPER - (int)(key & 0xffffffffu);
        g_sel[b * KSEL + r] = b * NPER + i;
    }
}

// ---------------- selected-row layer-2 transform, compacted output -----------
// H2c[m,:] = relu((agg2[sel[m],:] @ W2) * norm_dst[sel[m]] + b2),  m in [0,NSEL)
__global__ __launch_bounds__(256) void k_selgemm(const float* __restrict__ A,
                                                 const float* __restrict__ W,
                                                 const float* __restrict__ bias,
                                                 float* __restrict__ Out) {
    const int TM = 64;
    __shared__ float As[TM][32];
    __shared__ float Bs[32][HID];
    __shared__ int   ssel[TM];
    int t  = threadIdx.x;
    int tx = t & 31;
    int ty = t >> 5;
    int row0 = blockIdx.x * TM;       // grid = NSEL/TM = 625, exact

    if (t < TM) ssel[t] = g_sel[row0 + t];
    __syncthreads();

    float acc[8][4];
#pragma unroll
    for (int r = 0; r < 8; r++)
#pragma unroll
        for (int c = 0; c < 4; c++) acc[r][c] = 0.f;

    for (int kk = 0; kk < HID; kk += 32) {
#pragma unroll
        for (int j = 0; j < 8; j++) {
            int m = t + j * 256;
            int r = m >> 5, c = m & 31;
            As[r][c] = A[(size_t)ssel[r] * HID + kk + c];
        }
#pragma unroll
        for (int j = 0; j < 16; j++) {
            int m = t + j * 256;
            int r = m >> 7, c = m & 127;
            Bs[r][c] = W[(size_t)(kk + r) * HID + c];
        }
        __syncthreads();
#pragma unroll
        for (int k4 = 0; k4 < 8; k4++) {
            float4 b0 = *(const float4*)&Bs[k4 * 4 + 0][tx * 4];
            float4 b1 = *(const float4*)&Bs[k4 * 4 + 1][tx * 4];
            float4 b2 = *(const float4*)&Bs[k4 * 4 + 2][tx * 4];
            float4 b3 = *(const float4*)&Bs[k4 * 4 + 3][tx * 4];
#pragma unroll
            for (int r = 0; r < 8; r++) {
                float4 a = *(const float4*)&As[ty * 8 + r][k4 * 4];
                acc[r][0] += a.x * b0.x + a.y * b1.x + a.z * b2.x + a.w * b3.x;
                acc[r][1] += a.x * b0.y + a.y * b1.y + a.z * b2.y + a.w * b3.y;
                acc[r][2] += a.x * b0.z + a.y * b1.z + a.z * b2.z + a.w * b3.z;
                acc[r][3] += a.x * b0.w + a.y * b1.w + a.z * b2.w + a.w * b3.w;
            }
        }
        __syncthreads();
    }
#pragma unroll
    for (int r = 0; r < 8; r++) {
        int m    = row0 + ty * 8 + r;       // compact index, always < NSEL
        int node = ssel[ty * 8 + r];
        float nd = g_norm_dst[node];
        float4 b = __ldg((const float4*)bias + tx);
        float4 o;
        o.x = fmaxf(acc[r][0] * nd + b.x, 0.f);
        o.y = fmaxf(acc[r][1] * nd + b.y, 0.f);
        o.z = fmaxf(acc[r][2] * nd + b.z, 0.f);
        o.w = fmaxf(acc[r][3] * nd + b.w, 0.f);
        *(float4*)&Out[(size_t)m * HID + tx * 4] = o;
    }
}

// ---------------- output: smem-staged pooled @ W3, W3 reused across batches ----
// W3 slice staged TRANSPOSED (stride 132 = float4-aligned, ~2-way conflicts);
// H2c rows are compact & rank-ordered -> contiguous float4 staging.
#define WT_STR   132
#define WT_Q     (NCLS * WT_STR)                       // 2376 floats per rank
#define FIN_SMEM ((RPB * WT_Q + BATCH * RPB * HID) * (int)sizeof(float))  // 108800 B

extern __shared__ float s_fin[];

__global__ __launch_bounds__(256) void k_final(const float* __restrict__ H2c,
                                               const float* __restrict__ W3) {
    int t  = threadIdx.x;
    int r0 = blockIdx.x * RPB;

    float* sWT = s_fin;                       // RPB*WT_Q floats
    float* sX  = s_fin + RPB * WT_Q;          // BATCH*RPB*HID floats

    const float4* wsrc = (const float4*)(W3 + (size_t)r0 * HID * NCLS);
    const int WV = RPB * HID * NCLS / 4;      // 4608 float4
    for (int m4 = t; m4 < WV; m4 += 256) {
        float4 w = __ldg(wsrc + m4);
        int m = m4 * 4;
#pragma unroll
        for (int j = 0; j < 4; j++) {
            int mm = m + j;
            int q  = mm / (HID * NCLS);
            int r  = mm % (HID * NCLS);
            int h  = r / NCLS;
            int c  = r % NCLS;
            float val = (j == 0) ? w.x : (j == 1) ? w.y : (j == 2) ? w.z : w.w;
            sWT[q * WT_Q + c * WT_STR + h] = val;
        }
    }

    // stage 64 H2c rows (8 batches x 8 ranks) — contiguous compact layout
    {
        int warp = t >> 5, lane = t & 31;
        for (int p = warp; p < BATCH * RPB; p += 8) {
            int b = p >> 3, q = p & 7;
            ((float4*)sX)[p * (HID / 4) + lane] =
                __ldg((const float4*)(H2c + (size_t)(b * KSEL + r0 + q) * HID) + lane);
        }
    }
    __syncthreads();

    __shared__ float red[RPB * NCLS];
    for (int b = 0; b < BATCH; b++) {
        if (t < RPB * NCLS) {
            int q = t / NCLS, c = t % NCLS;
            const float4* x = (const float4*)(sX + (b * RPB + q) * HID);
            const float4* w = (const float4*)(sWT + q * WT_Q + c * WT_STR);
            float acc = 0.f;
#pragma unroll 8
            for (int h4 = 0; h4 < HID / 4; h4++) {
                float4 xv = x[h4];
                float4 wv = w[h4];
                acc += xv.x * wv.x + xv.y * wv.y + xv.z * wv.z + xv.w * wv.w;
            }
            red[t] = acc;
        }
        __syncthreads();
        if (t < NCLS) {
            float s = 0.f;
#pragma unroll
            for (int q = 0; q < RPB; q++) s += red[q * NCLS + t];
            g_partial[((size_t)b * FIN_BLK + blockIdx.x) * NCLS + t] = s;
        }
        __syncthreads();
    }
}

// warp-per-output reduction: 18 blocks x 256 threads = 144 warps = BATCH*NCLS
__global__ __launch_bounds__(256) void k_reduce(const float* __restrict__ b3,
                                                float* __restrict__ out) {
    int w    = blockIdx.x * 8 + (threadIdx.x >> 5);
    int lane = threadIdx.x & 31;
    if (w >= BATCH * NCLS) return;
    int b = w / NCLS, c = w % NCLS;
    float s = 0.f;
    for (int blk = lane; blk < FIN_BLK; blk += 32)
        s += g_partial[((size_t)b * FIN_BLK + blk) * NCLS + c];
#pragma unroll
    for (int off = 16; off > 0; off >>= 1)
        s += __shfl_down_sync(0xffffffffu, s, off);
    if (lane == 0) out[w] = s + __ldg(&b3[c]);
}

// ---------------- launch ----------------
extern "C" void kernel_launch(void* const* d_in, const int* in_sizes, int n_in,
                              void* d_out, int out_size) {
    const float* features = (const float*)d_in[0];
    const int*   src      = (const int*)  d_in[1];
    const int*   dst      = (const int*)  d_in[2];
    const float* W1       = (const float*)d_in[3];
    const float* b1       = (const float*)d_in[4];
    const float* W2       = (const float*)d_in[5];
    const float* b2       = (const float*)d_in[6];
    const float* W3       = (const float*)d_in[7];
    const float* b3       = (const float*)d_in[8];
    float* out = (float*)d_out;

    float *bufA, *bufB;
    cudaGetSymbolAddress((void**)&bufA, g_bufA);
    cudaGetSymbolAddress((void**)&bufB, g_bufB);

    cudaFuncSetAttribute(k_sort, cudaFuncAttributeMaxDynamicSharedMemorySize,
                         SORT_M * (int)sizeof(unsigned long long));
    cudaFuncSetAttribute(k_final, cudaFuncAttributeMaxDynamicSharedMemorySize,
                         FIN_SMEM);

    // 1) degrees
    k_zero_deg<<<(NN + 255) / 256, 256>>>();
    k_degrees<<<(EE / 2 + 255) / 256, 256>>>(src, dst);

    // 2) CSR by dst (parallel 3-pass scan w/ fused norms, then scatter)
    k_scan_a<<<SCAN_G, SCAN_B>>>();
    k_scan_b<<<1, 512>>>();
    k_scan_c<<<SCAN_G, SCAN_B>>>();
    k_csr_scatter<<<(EE + 255) / 256, 256>>>(src, dst);

    // 3) layer 1: aggregate in 64-dim (fused ns), transform + relu(*nd + b1)
    k_agg64<<<(NN * 32 + 255) / 256, 256>>>(features, bufB);
    k_gemm1<<<(NN + 63) / 64, 256>>>(bufB, W1, b1, bufA);            // bufA = h1

    // 4) layer 2, aggregate-first: agg2 = seg_sum(h1*ns); then only what's needed
    k_agg128<<<(NN * 32 + 255) / 256, 256>>>(bufA, bufB);            // bufB = agg2
    k_colgemm<<<(NN * 32 + 255) / 256, 256>>>(bufB, W2, b2);         // g_keyf

    // 5) exact per-batch top-K (register-blocked bitonic sort on compact keys)
    k_sort<<<BATCH, 1024, SORT_M * sizeof(unsigned long long)>>>();

    // 6) full layer-2 transform ONLY for selected rows, compacted in rank order
    k_selgemm<<<NSEL / 64, 256>>>(bufB, W2, b2, bufA);               // bufA = H2c

    // 7) pooled @ W3 + b3 (transposed W slice shared across batches; deterministic)
    k_final<<<FIN_BLK, 256, FIN_SMEM>>>(bufA, W3);
    k_reduce<<<18, 256>>>(b3, out);
}